// round 13
// baseline (speedup 1.0000x reference)
#include <cuda_runtime.h>
#include <cuda_fp16.h>
#include <math.h>
#include <stdint.h>

// ---------------- problem constants ----------------
#define NN   8
#define CIN  256
#define C2   128
#define HH   128
#define WW   128
#define GG   8
#define PP   (HH*WW)      // 16384
#define HS   64
#define WS   64
#define PS   (HS*WS)      // 4096

// ---------------- scratch (device globals; no allocation) ----------------
__device__ __half g_tsp  [NN*C2*PS];     // conv+bn(sp) at 64x64, fp16
__device__ __half g_cs   [NN*2*C2*PP];   // [cp1 | sp1] 256ch, fp16
__device__ __half g_cat  [NN*192*PP];    // [redim(128) | fdir(32) | fdist(32)], fp16
__device__ __half g_sp_up[NN*CIN*PP];    // upsampled raw sp, fp16 (67MB)
__device__ float  g_sim  [NN*GG*PP];
__device__ float  g_off  [NN*32*PP];

// =====================================================================
// shared MMA helpers (1-term fp16)
// =====================================================================
#define GEMM_SMEM 32768

__device__ __forceinline__ uint32_t smem_u32(const void* p) {
    uint32_t a;
    asm("{ .reg .u64 t; cvta.to.shared.u64 t, %1; cvt.u32.u64 %0, t; }"
        : "=r"(a) : "l"(p));
    return a;
}
__device__ __forceinline__ uint32_t pack2h(float a, float b) {
    return (uint32_t)__half_as_ushort(__float2half_rn(a))
         | ((uint32_t)__half_as_ushort(__float2half_rn(b)) << 16);
}
__device__ __forceinline__ void ldmx4(uint32_t* r, uint32_t addr) {
    asm volatile("ldmatrix.sync.aligned.m8n8.x4.shared.b16 {%0,%1,%2,%3}, [%4];"
                 : "=r"(r[0]), "=r"(r[1]), "=r"(r[2]), "=r"(r[3]) : "r"(addr));
}
__device__ __forceinline__ void ldmx4t(uint32_t* r, uint32_t addr) {
    asm volatile("ldmatrix.sync.aligned.m8n8.x4.trans.shared.b16 {%0,%1,%2,%3}, [%4];"
                 : "=r"(r[0]), "=r"(r[1]), "=r"(r[2]), "=r"(r[3]) : "r"(addr));
}
__device__ __forceinline__ void mma16816(float* c, const uint32_t* a, const uint32_t* b) {
    asm volatile("mma.sync.aligned.m16n8k16.row.col.f32.f16.f16.f32 "
                 "{%0,%1,%2,%3}, {%4,%5,%6,%7}, {%8,%9}, {%0,%1,%2,%3};"
                 : "+f"(c[0]), "+f"(c[1]), "+f"(c[2]), "+f"(c[3])
                 : "r"(a[0]), "r"(a[1]), "r"(a[2]), "r"(a[3]), "r"(b[0]), "r"(b[1]));
}
__device__ __forceinline__ uint32_t swzA(uint32_t bo) { return bo ^ (((bo >> 7) & 7) << 4); }
__device__ __forceinline__ uint32_t swzB(uint32_t bo) { return bo ^ (((bo >> 8) & 7) << 4); }

// =====================================================================
// 128-out 1x1 conv GEMM (1-term fp16), templated input/output dtype
// =====================================================================
template<typename TIN, typename TOUT>
__global__ void __launch_bounds__(256, 2) gemm_mma_kernel(
    const TIN* __restrict__ X, const float* __restrict__ Wm,
    const float* __restrict__ gscale, const float* __restrict__ bias,
    TOUT* __restrict__ Y, int Pn, long xns, long yns, int relu)
{
    extern __shared__ char smem[];
    char* ahs = smem;               // [128co][64k] fp16  16KB
    char* bhs = smem + 16384;       // [64k][128px] fp16  16KB

    const int t  = threadIdx.x;
    const int l  = t & 31, w = t >> 5;
    const int wm = w & 1, wn = w >> 1;
    const int n  = blockIdx.y, p0 = blockIdx.x * 128;
    const TIN* Xn = X + (long)n * xns;
    TOUT*      Yn = Y + (long)n * yns;

    const uint32_t ah0 = smem_u32(ahs);
    const uint32_t bh0 = smem_u32(bhs);

    float acc[4][4][4];
#pragma unroll
    for (int i = 0; i < 4; i++)
#pragma unroll
        for (int j = 0; j < 4; j++)
#pragma unroll
            for (int q = 0; q < 4; q++) acc[i][j][q] = 0.f;

    const int arow  = wm * 64 + (l & 15);
    const int akoff = (l >> 4) * 8;
    const int brow  = (l & 15);
    const int bnoff = wn * 32 + (l >> 4) * 8;

    for (int c = 0; c < 4; c++) {
        const int k0 = c * 64;
        __syncthreads();
        // ---- stage A (weights, fp16) ----
#pragma unroll
        for (int i = 0; i < 4; i++) {
            int idx = t + i * 256;
            int row = idx >> 3, ch = idx & 7;
            const float* wp = Wm + (long)row * 256 + k0 + ch * 8;
            float4 v0 = *(const float4*)wp;
            float4 v1 = *(const float4*)(wp + 4);
            uint4 h4;
            h4.x = pack2h(v0.x, v0.y);
            h4.y = pack2h(v0.z, v0.w);
            h4.z = pack2h(v1.x, v1.y);
            h4.w = pack2h(v1.z, v1.w);
            *(uint4*)(ahs + swzA(row * 128 + ch * 16)) = h4;
        }
        // ---- stage B (inputs, fp16) ----
#pragma unroll
        for (int i = 0; i < 4; i++) {
            int idx = t + i * 256;
            int k = idx >> 4, ch = idx & 15;
            if constexpr (sizeof(TIN) == 4) {
                const float* xp = (const float*)Xn + (long)(k0 + k) * Pn + p0 + ch * 8;
                float4 v0 = *(const float4*)xp;
                float4 v1 = *(const float4*)(xp + 4);
                uint4 h4;
                h4.x = pack2h(v0.x, v0.y);
                h4.y = pack2h(v0.z, v0.w);
                h4.z = pack2h(v1.x, v1.y);
                h4.w = pack2h(v1.z, v1.w);
                *(uint4*)(bhs + swzB(k * 256 + ch * 16)) = h4;
            } else {
                const __half* xp = (const __half*)Xn + (long)(k0 + k) * Pn + p0 + ch * 8;
                *(uint4*)(bhs + swzB(k * 256 + ch * 16)) = *(const uint4*)xp;
            }
        }
        __syncthreads();

#pragma unroll
        for (int ks = 0; ks < 4; ks++) {
            uint32_t a[4][4];
            uint32_t B[2][4];
#pragma unroll
            for (int i = 0; i < 4; i++) {
                uint32_t bo = (uint32_t)((arow + i * 16) * 128 + (akoff + ks * 16) * 2);
                ldmx4(a[i], ah0 + swzA(bo));
            }
#pragma unroll
            for (int j2 = 0; j2 < 2; j2++) {
                uint32_t bo = (uint32_t)((brow + ks * 16) * 256 + (bnoff + j2 * 16) * 2);
                ldmx4t(B[j2], bh0 + swzB(bo));
            }
#pragma unroll
            for (int i = 0; i < 4; i++)
#pragma unroll
                for (int j = 0; j < 4; j++)
                    mma16816(acc[i][j], a[i], &B[j >> 1][(j & 1) * 2]);
        }
    }

    const float bnfac = rsqrtf(1.f + 1e-5f);
    const int gid = l >> 2, tig = l & 3;
#pragma unroll
    for (int i = 0; i < 4; i++) {
        int co0 = wm * 64 + i * 16 + gid;
        int co1 = co0 + 8;
        float s0 = gscale ? gscale[co0] * bnfac : 1.f;
        float s1 = gscale ? gscale[co1] * bnfac : 1.f;
        float b0 = bias[co0], b1 = bias[co1];
#pragma unroll
        for (int j = 0; j < 4; j++) {
            int col = p0 + wn * 32 + j * 8 + 2 * tig;
            float2 r0, r1;
            r0.x = acc[i][j][0] * s0 + b0;
            r0.y = acc[i][j][1] * s0 + b0;
            r1.x = acc[i][j][2] * s1 + b1;
            r1.y = acc[i][j][3] * s1 + b1;
            if (relu) {
                r0.x = fmaxf(r0.x, 0.f); r0.y = fmaxf(r0.y, 0.f);
                r1.x = fmaxf(r1.x, 0.f); r1.y = fmaxf(r1.y, 0.f);
            }
            if constexpr (sizeof(TOUT) == 4) {
                *(float2*)((float*)Yn + (long)co0 * Pn + col) = r0;
                *(float2*)((float*)Yn + (long)co1 * Pn + col) = r1;
            } else {
                *(__half2*)((__half*)Yn + (long)co0 * Pn + col) = __floats2half2_rn(r0.x, r0.y);
                *(__half2*)((__half*)Yn + (long)co1 * Pn + col) = __floats2half2_rn(r1.x, r1.y);
            }
        }
    }
}

// =====================================================================
// fdist: 3x3 conv 128->32 on |cp1-sp1| (fp16) as HMMA implicit GEMM (1-term)
// =====================================================================
#define FDB_H   28160      // [3][130][36] ushort
#define FDA_H   18944      // [32][296] ushort
#define FD_SMEM (FDB_H + FDA_H)   // 47104

__global__ void __launch_bounds__(256, 2) fdist_mma_kernel(
    const float* __restrict__ wD, const float* __restrict__ bD)
{
    extern __shared__ char smem[];
    ushort* Bh = (ushort*)smem;
    ushort* Ah = (ushort*)(smem + FDB_H);

    const int t = threadIdx.x, l = t & 31, w = t >> 5;
    const int y = blockIdx.x, n = blockIdx.y;
    const int n0 = w * 16;
    const __half* csn = g_cs + (long)n * (2*C2*PP);

    float acc[2][2][4];
#pragma unroll
    for (int m = 0; m < 2; m++)
#pragma unroll
        for (int j = 0; j < 2; j++)
#pragma unroll
            for (int q = 0; q < 4; q++) acc[m][j][q] = 0.f;

    const uint32_t ah0 = smem_u32(Ah);

    for (int c0 = 0; c0 < C2; c0 += 32) {
        __syncthreads();
        if (t < 96) {
            int r = t >> 5, c = t & 31;
            Bh[(r * 130 + 0)   * 36 + c] = 0;
            Bh[(r * 130 + 129) * 36 + c] = 0;
        }
        for (int i = t; i < 3072; i += 256) {
            int r = i >> 10;
            int c = (i >> 5) & 31;
            int q = i & 31;
            int ys = y + r - 1;
            int px = q * 4;
            int ib = (r * 130 + 1 + px) * 36 + c;
            if (ys >= 0 && ys < HH) {
                long off = (long)(c0 + c) * PP + ys * WW + px;
                __half2 a0 = *(const __half2*)(csn + off);
                __half2 a1 = *(const __half2*)(csn + off + 2);
                __half2 b0 = *(const __half2*)(csn + off + (long)C2 * PP);
                __half2 b1 = *(const __half2*)(csn + off + (long)C2 * PP + 2);
                __half2 d0 = __habs2(__hsub2(a0, b0));
                __half2 d1 = __habs2(__hsub2(a1, b1));
                Bh[ib]       = __half_as_ushort(__low2half(d0));
                Bh[ib + 36]  = __half_as_ushort(__high2half(d0));
                Bh[ib + 72]  = __half_as_ushort(__low2half(d1));
                Bh[ib + 108] = __half_as_ushort(__high2half(d1));
            } else {
                Bh[ib] = 0; Bh[ib + 36] = 0; Bh[ib + 72] = 0; Bh[ib + 108] = 0;
            }
        }
        for (int i = t; i < 32 * 288; i += 256) {
            int co = i / 288, kp = i % 288;
            int tap = kp >> 5, cl = kp & 31;
            Ah[co * 296 + kp] =
                __half_as_ushort(__float2half_rn(wD[co * 1152 + (c0 + cl) * 9 + tap]));
        }
        __syncthreads();

#pragma unroll
        for (int tap = 0; tap < 9; tap++) {
            const int dy = tap / 3, dx = tap % 3;
#pragma unroll
            for (int ks = 0; ks < 2; ks++) {
                uint32_t ahf[2][4];
#pragma unroll
                for (int m = 0; m < 2; m++) {
                    uint32_t ao = (uint32_t)((m * 16 + (l & 15)) * 296
                                  + tap * 32 + ks * 16 + (l >> 4) * 8) * 2;
                    ldmx4(ahf[m], ah0 + ao);
                }
                uint32_t bhf[2][2];
#pragma unroll
                for (int j2 = 0; j2 < 2; j2++) {
                    int px = n0 + j2 * 8 + (l >> 2) + dx;
                    int c  = ks * 16 + (l & 3) * 2;
                    int ib = (dy * 130 + px) * 36 + c;
                    bhf[j2][0] = *(const uint32_t*)&Bh[ib];
                    bhf[j2][1] = *(const uint32_t*)&Bh[ib + 8];
                }
#pragma unroll
                for (int m = 0; m < 2; m++)
#pragma unroll
                    for (int j2 = 0; j2 < 2; j2++)
                        mma16816(acc[m][j2], ahf[m], bhf[j2]);
            }
        }
    }

    __half* outp = g_cat + (long)n * (192 * PP) + (long)160 * PP + y * WW;
#pragma unroll
    for (int m = 0; m < 2; m++) {
        int co = m * 16 + (l >> 2);
        float b0 = bD[co], b1 = bD[co + 8];
#pragma unroll
        for (int j2 = 0; j2 < 2; j2++) {
            int px = n0 + j2 * 8 + (l & 3) * 2;
            *(__half2*)(outp + (long)co * PP + px) =
                __floats2half2_rn(acc[m][j2][0] + b0, acc[m][j2][1] + b0);
            *(__half2*)(outp + (long)(co + 8) * PP + px) =
                __floats2half2_rn(acc[m][j2][2] + b1, acc[m][j2][3] + b1);
        }
    }
}

// =====================================================================
// fdir: 3x3 conv 8->32 on sim as HMMA implicit GEMM (1-term)
// =====================================================================
__global__ void __launch_bounds__(256, 2) fdir_mma_kernel(
    const float* __restrict__ wd, const float* __restrict__ bd)
{
    __shared__ ushort Bs[3 * 130 * 8];   // [row][halo px][ch]
    __shared__ ushort Ah[32 * 88];

    const int t = threadIdx.x, l = t & 31, w = t >> 5;
    const int y = blockIdx.x, n = blockIdx.y;
    const int n0 = w * 16;
    const float* simn = g_sim + (long)n * GG * PP;

    for (int i = t; i < 32 * 88; i += 256) {
        int co = i / 88, kp = i % 88;
        ushort h = 0;
        if (kp < 72) {
            int tap = kp >> 3, c = kp & 7;
            h = __half_as_ushort(__float2half_rn(wd[co * 72 + c * 9 + tap]));
        }
        Ah[i] = h;
    }
    if (t < 48) {
        int r = t >> 4, side = (t >> 3) & 1, c = t & 7;
        Bs[(r * 130 + (side ? 129 : 0)) * 8 + c] = 0;
    }
    for (int i = t; i < 1536; i += 256) {
        int r = i >> 9;
        int c = (i >> 6) & 7;
        int q = i & 63;
        int px = q * 2;
        int ys = y + r - 1;
        int ib = (r * 130 + 1 + px) * 8 + c;
        if (ys >= 0 && ys < HH) {
            float2 v = *(const float2*)(simn + (long)c * PP + ys * WW + px);
            Bs[ib]     = __half_as_ushort(__float2half_rn(v.x));
            Bs[ib + 8] = __half_as_ushort(__float2half_rn(v.y));
        } else {
            Bs[ib] = 0; Bs[ib + 8] = 0;
        }
    }
    __syncthreads();

    const uint32_t ah0 = smem_u32(Ah);

    float acc[2][2][4];
#pragma unroll
    for (int m = 0; m < 2; m++)
#pragma unroll
        for (int j = 0; j < 2; j++)
#pragma unroll
            for (int q = 0; q < 4; q++) acc[m][j][q] = 0.f;

    const int cfrag = (l & 3) * 2;
#pragma unroll
    for (int ks = 0; ks < 5; ks++) {
        uint32_t ahf[2][4];
#pragma unroll
        for (int m = 0; m < 2; m++) {
            uint32_t ao = (uint32_t)((m * 16 + (l & 15)) * 88 + ks * 16 + (l >> 4) * 8) * 2;
            ldmx4(ahf[m], ah0 + ao);
        }
        const int tap_a = 2 * ks, tap_b = 2 * ks + 1;
        const int dya = tap_a / 3, dxa = tap_a % 3;
        const int dyb = tap_b / 3, dxb = tap_b % 3;
        uint32_t bhf[2][2];
#pragma unroll
        for (int j2 = 0; j2 < 2; j2++) {
            int pxb = n0 + j2 * 8 + (l >> 2);
            bhf[j2][0] = *(const uint32_t*)&Bs[((dya * 130) + pxb + dxa) * 8 + cfrag];
            bhf[j2][1] = (tap_b < 9)
                ? *(const uint32_t*)&Bs[((dyb * 130) + pxb + dxb) * 8 + cfrag]
                : 0u;
        }
#pragma unroll
        for (int m = 0; m < 2; m++)
#pragma unroll
            for (int j2 = 0; j2 < 2; j2++)
                mma16816(acc[m][j2], ahf[m], bhf[j2]);
    }

    __half* outp = g_cat + (long)n * (192 * PP) + (long)128 * PP + y * WW;
#pragma unroll
    for (int m = 0; m < 2; m++) {
        int co = m * 16 + (l >> 2);
        float b0 = bd[co], b1 = bd[co + 8];
#pragma unroll
        for (int j2 = 0; j2 < 2; j2++) {
            int px = n0 + j2 * 8 + (l & 3) * 2;
            *(__half2*)(outp + (long)co * PP + px) =
                __floats2half2_rn(acc[m][j2][0] + b0, acc[m][j2][1] + b0);
            *(__half2*)(outp + (long)(co + 8) * PP + px) =
                __floats2half2_rn(acc[m][j2][2] + b1, acc[m][j2][3] + b1);
        }
    }
}

// =====================================================================
// off: 1x1 conv 192->32 as HMMA GEMM (1-term, fp16 input from g_cat)
// =====================================================================
#define OFA_H 12800          // [32][200] ushort
#define OFB_H 16384          // [64][128px] ushort
#define OFF_SMEM (OFA_H + OFB_H)   // 29184

__global__ void __launch_bounds__(256, 2) off_mma_kernel(
    const float* __restrict__ wo, const float* __restrict__ bo)
{
    extern __shared__ char smem[];
    ushort* Ah = (ushort*)smem;
    char*   bhs = smem + OFA_H;

    const int t = threadIdx.x, l = t & 31, w = t >> 5;
    const int n = blockIdx.y, p0 = blockIdx.x * 128;
    const __half* xn = g_cat + (long)n * (192 * PP);

    for (int i = t; i < 32 * 192; i += 256) {
        int co = i / 192, k = i % 192;
        Ah[co * 200 + k] = __half_as_ushort(__float2half_rn(wo[co * 192 + k]));
    }

    float acc[2][2][4];
#pragma unroll
    for (int m = 0; m < 2; m++)
#pragma unroll
        for (int j = 0; j < 2; j++)
#pragma unroll
            for (int q = 0; q < 4; q++) acc[m][j][q] = 0.f;

    const uint32_t ah0 = smem_u32(Ah);
    const uint32_t bh0 = smem_u32(bhs);
    const int brow  = l & 15;
    const int bnoff = w * 16 + (l >> 4) * 8;

    for (int kc = 0; kc < 3; kc++) {
        const int k0 = kc * 64;
        __syncthreads();
#pragma unroll
        for (int i = 0; i < 4; i++) {
            int idx = t + i * 256;
            int k = idx >> 4, ch = idx & 15;
            const __half* xp = xn + (long)(k0 + k) * PP + p0 + ch * 8;
            *(uint4*)(bhs + swzB(k * 256 + ch * 16)) = *(const uint4*)xp;
        }
        __syncthreads();

#pragma unroll
        for (int ks = 0; ks < 4; ks++) {
            uint32_t ahf[2][4];
#pragma unroll
            for (int m = 0; m < 2; m++) {
                uint32_t ao = (uint32_t)((m * 16 + (l & 15)) * 200
                              + k0 + ks * 16 + (l >> 4) * 8) * 2;
                ldmx4(ahf[m], ah0 + ao);
            }
            uint32_t Bhf[4];
            ldmx4t(Bhf, bh0 + swzB((uint32_t)((brow + ks * 16) * 256 + bnoff * 2)));
#pragma unroll
            for (int m = 0; m < 2; m++)
#pragma unroll
                for (int j2 = 0; j2 < 2; j2++)
                    mma16816(acc[m][j2], ahf[m], &Bhf[j2 * 2]);
        }
    }

    float* outp = g_off + (long)n * (32 * PP) + p0;
#pragma unroll
    for (int m = 0; m < 2; m++) {
        int co = m * 16 + (l >> 2);
        float b0 = bo[co], b1 = bo[co + 8];
#pragma unroll
        for (int j2 = 0; j2 < 2; j2++) {
            int px = w * 16 + j2 * 8 + (l & 3) * 2;
            outp[(long)co * PP + px]           = acc[m][j2][0] + b0;
            outp[(long)co * PP + px + 1]       = acc[m][j2][1] + b0;
            outp[(long)(co + 8) * PP + px]     = acc[m][j2][2] + b1;
            outp[(long)(co + 8) * PP + px + 1] = acc[m][j2][3] + b1;
        }
    }
}

// ---------------- bilinear upsample 64->128 of raw sp -> fp16 ----------------
__global__ void __launch_bounds__(256) up_sp_kernel(const float* __restrict__ sp)
{
    long gid = (long)blockIdx.x * 256 + threadIdx.x;   // over NN*CIN*PP
    int x = gid & 127;
    int y = (gid >> 7) & 127;
    long nc = gid >> 14;
    float ysf = y * (63.f / 127.f);
    int y0 = (int)ysf; float wy = ysf - y0; int y1 = min(y0 + 1, 63);
    float xsf = x * (63.f / 127.f);
    int x0 = (int)xsf; float wx = xsf - x0; int x1 = min(x0 + 1, 63);
    const float* b = sp + nc * PS;
    float v = (b[y0*WS + x0] * (1.f - wx) + b[y0*WS + x1] * wx) * (1.f - wy)
            + (b[y1*WS + x0] * (1.f - wx) + b[y1*WS + x1] * wx) * wy;
    g_sp_up[gid] = __float2half_rn(v);
}

// ---------------- upsample conv+bn(sp) (fp16), relu, into g_cs[128:] ----------------
__global__ void __launch_bounds__(256) up_relu_kernel()
{
    long gid = (long)blockIdx.x * 256 + threadIdx.x;
    int x = gid & 127;
    int y = (gid >> 7) & 127;
    int c = (int)((gid >> 14) & 127);
    int n = (int)(gid >> 21);
    float ysf = y * (63.f / 127.f);
    int y0 = (int)ysf; float wy = ysf - y0; int y1 = min(y0 + 1, 63);
    float xsf = x * (63.f / 127.f);
    int x0 = (int)xsf; float wx = xsf - x0; int x1 = min(x0 + 1, 63);
    const __half* b = g_tsp + ((long)n * C2 + c) * PS;
    float v = (__half2float(b[y0*WS + x0]) * (1.f - wx) + __half2float(b[y0*WS + x1]) * wx) * (1.f - wy)
            + (__half2float(b[y1*WS + x0]) * (1.f - wx) + __half2float(b[y1*WS + x1]) * wx) * wy;
    g_cs[(long)n * (2*C2*PP) + (long)(C2 + c) * PP + (y * WW + x)] =
        __float2half_rn(fmaxf(v, 0.f));
}

// ---------------- group cosine similarity (fp16 inputs, 2 px/thread) ----------------
__global__ void __launch_bounds__(256) sim_kernel()
{
    long gid = (long)blockIdx.x * 256 + threadIdx.x;  // over NN*GG*PP/2
    int p2 = (int)(gid & (PP/2 - 1));
    int g  = (int)((gid >> 13) & 7);
    int n  = (int)(gid >> 16);
    const __half* a = g_cs + (long)n * (2*C2*PP) + (long)(g * 16) * PP + 2 * p2;
    const __half* b = a + (long)C2 * PP;
    float2 num = {0.f, 0.f}, na = {0.f, 0.f}, nb = {0.f, 0.f};
#pragma unroll
    for (int cc = 0; cc < 16; cc++) {
        float2 af = __half22float2(*(const __half2*)(a + (long)cc * PP));
        float2 bf = __half22float2(*(const __half2*)(b + (long)cc * PP));
        num.x += af.x * bf.x; num.y += af.y * bf.y;
        na.x  += af.x * af.x; na.y  += af.y * af.y;
        nb.x  += bf.x * bf.x; nb.y  += bf.y * bf.y;
    }
    float2 s;
    s.x = num.x / (fmaxf(sqrtf(na.x), 1e-8f) * fmaxf(sqrtf(nb.x), 1e-8f));
    s.y = num.y / (fmaxf(sqrtf(na.y), 1e-8f) * fmaxf(sqrtf(nb.y), 1e-8f));
    *(float2*)(g_sim + gid * 2) = s;
}

// ---------------- final: dual grid_sample + add ----------------
__device__ __forceinline__ void make_taps(int x, int y, float ox, float oy,
                                          int* idx, float* wgt)
{
    float gx = x * (2.f / 127.f) - 1.f + ox * (1.f / 128.f);
    float gy = y * (2.f / 127.f) - 1.f + oy * (1.f / 128.f);
    float px = (gx + 1.f) * 0.5f * 127.f;
    float py = (gy + 1.f) * 0.5f * 127.f;
    float x0f = floorf(px), y0f = floorf(py);
    float wx = px - x0f, wy = py - y0f;
    int x0 = (int)x0f, y0 = (int)y0f, x1 = x0 + 1, y1 = y0 + 1;
    bool vx0 = (x0 >= 0) && (x0 <= 127), vx1 = (x1 >= 0) && (x1 <= 127);
    bool vy0 = (y0 >= 0) && (y0 <= 127), vy1 = (y1 >= 0) && (y1 <= 127);
    int cx0 = min(max(x0, 0), 127), cx1 = min(max(x1, 0), 127);
    int cy0 = min(max(y0, 0), 127), cy1 = min(max(y1, 0), 127);
    idx[0] = cy0 * WW + cx0; wgt[0] = (vx0 && vy0) ? (1.f - wx) * (1.f - wy) : 0.f;
    idx[1] = cy0 * WW + cx1; wgt[1] = (vx1 && vy0) ? wx * (1.f - wy) : 0.f;
    idx[2] = cy1 * WW + cx0; wgt[2] = (vx0 && vy1) ? (1.f - wx) * wy : 0.f;
    idx[3] = cy1 * WW + cx1; wgt[3] = (vx1 && vy1) ? wx * wy : 0.f;
}

__global__ void __launch_bounds__(128) sample_kernel(const float* __restrict__ cp,
                                                     float* __restrict__ out)
{
    int x  = threadIdx.x;
    int y  = blockIdx.x;
    int ng = blockIdx.y;
    int n  = ng >> 3, gi = ng & 7;
    int p  = (y << 7) | x;
    const float* offn = g_off + (long)n * (32*PP) + p;
    float olx = offn[(long)(2*gi)      * PP];
    float oly = offn[(long)(2*gi + 1)  * PP];
    float ohx = offn[(long)(16 + 2*gi) * PP];
    float ohy = offn[(long)(17 + 2*gi) * PP];

    int il[4], ih[4];
    float wl[4], wh[4];
    make_taps(x, y, olx, oly, il, wl);
    make_taps(x, y, ohx, ohy, ih, wh);

    long cbase = ((long)n * CIN + gi * 32) * PP;
    const float*  cpp = cp + cbase;
    const __half* spp = g_sp_up + cbase;
    float* op = out + cbase + p;
#pragma unroll 4
    for (int c = 0; c < 32; c++) {
        const float*  a = cpp + (long)c * PP;
        const __half* s = spp + (long)c * PP;
        float v = wl[0]*a[il[0]] + wl[1]*a[il[1]] + wl[2]*a[il[2]] + wl[3]*a[il[3]]
                + wh[0]*__half2float(s[ih[0]]) + wh[1]*__half2float(s[ih[1]])
                + wh[2]*__half2float(s[ih[2]]) + wh[3]*__half2float(s[ih[3]]);
        op[(long)c * PP] = v;
    }
}

// ---------------- persistent host-side stream/event handles ----------------
static cudaStream_t g_s1 = nullptr, g_s2 = nullptr;
static cudaEvent_t  g_e0, g_e1, g_e2, g_e3, g_e4;
static bool g_init_done = false;

// ---------------- launch (fork/join stream overlap, capture-safe) ----------------
extern "C" void kernel_launch(void* const* d_in, const int* in_sizes, int n_in,
                              void* d_out, int out_size)
{
    const float* cp      = (const float*)d_in[0];
    const float* sp      = (const float*)d_in[1];
    const float* w_cp    = (const float*)d_in[2];
    const float* gb_cp   = (const float*)d_in[3];
    const float* b_cp    = (const float*)d_in[4];
    const float* w_sp    = (const float*)d_in[5];
    const float* gb_sp   = (const float*)d_in[6];
    const float* b_sp    = (const float*)d_in[7];
    const float* w_redim = (const float*)d_in[8];
    const float* b_redim = (const float*)d_in[9];
    const float* w_dir   = (const float*)d_in[10];
    const float* b_dir   = (const float*)d_in[11];
    const float* w_dist  = (const float*)d_in[12];
    const float* b_dist  = (const float*)d_in[13];
    const float* w_off   = (const float*)d_in[14];
    const float* b_off   = (const float*)d_in[15];
    float* out = (float*)d_out;

    __half *p_tsp, *p_cs, *p_cat;
    cudaGetSymbolAddress((void**)&p_tsp, g_tsp);
    cudaGetSymbolAddress((void**)&p_cs,  g_cs);
    cudaGetSymbolAddress((void**)&p_cat, g_cat);

    if (!g_init_done) {
        cudaStreamCreateWithFlags(&g_s1, cudaStreamNonBlocking);
        cudaStreamCreateWithFlags(&g_s2, cudaStreamNonBlocking);
        cudaEventCreateWithFlags(&g_e0, cudaEventDisableTiming);
        cudaEventCreateWithFlags(&g_e1, cudaEventDisableTiming);
        cudaEventCreateWithFlags(&g_e2, cudaEventDisableTiming);
        cudaEventCreateWithFlags(&g_e3, cudaEventDisableTiming);
        cudaEventCreateWithFlags(&g_e4, cudaEventDisableTiming);
        cudaFuncSetAttribute(gemm_mma_kernel<float, __half>,
                             cudaFuncAttributeMaxDynamicSharedMemorySize, GEMM_SMEM);
        cudaFuncSetAttribute(gemm_mma_kernel<__half, __half>,
                             cudaFuncAttributeMaxDynamicSharedMemorySize, GEMM_SMEM);
        cudaFuncSetAttribute(fdist_mma_kernel,
                             cudaFuncAttributeMaxDynamicSharedMemorySize, FD_SMEM);
        cudaFuncSetAttribute(off_mma_kernel,
                             cudaFuncAttributeMaxDynamicSharedMemorySize, OFF_SMEM);
        g_init_done = true;
    }
    cudaStream_t s1 = g_s1, s2 = g_s2;

    // ---- phase 1: {sp-gemm -> up_relu} on s1 || {up_sp} on s2 || {cp-gemm} on default ----
    cudaEventRecord(g_e0, 0);
    cudaStreamWaitEvent(s1, g_e0, 0);
    cudaStreamWaitEvent(s2, g_e0, 0);

    gemm_mma_kernel<float, __half><<<dim3(PS/128, NN), 256, GEMM_SMEM, s1>>>(
        sp, w_sp, gb_sp, b_sp, p_tsp, PS, (long)CIN*PS, (long)C2*PS, 0);
    up_relu_kernel<<<NN*C2*PP/256, 256, 0, s1>>>();

    up_sp_kernel<<<NN*CIN*PP/256, 256, 0, s2>>>(sp);

    gemm_mma_kernel<float, __half><<<dim3(PP/128, NN), 256, GEMM_SMEM>>>(
        cp, w_cp, gb_cp, b_cp, p_cs, PP, (long)CIN*PP, (long)2*C2*PP, 1);

    cudaEventRecord(g_e1, s1);
    cudaStreamWaitEvent(0, g_e1, 0);

    // ---- phase 2: {redim} on default || {sim -> fdir} on s1 || {fdist} on s2 ----
    cudaEventRecord(g_e2, 0);
    cudaStreamWaitEvent(s1, g_e2, 0);
    cudaStreamWaitEvent(s2, g_e2, 0);

    gemm_mma_kernel<__half, __half><<<dim3(PP/128, NN), 256, GEMM_SMEM>>>(
        p_cs, w_redim, nullptr, b_redim, p_cat, PP, (long)2*C2*PP, (long)192*PP, 0);

    sim_kernel<<<NN*GG*(PP/2)/256, 256, 0, s1>>>();
    fdir_mma_kernel<<<dim3(HH, NN), 256, 0, s1>>>(w_dir, b_dir);

    fdist_mma_kernel<<<dim3(HH, NN), 256, FD_SMEM, s2>>>(w_dist, b_dist);

    cudaEventRecord(g_e3, s1);
    cudaEventRecord(g_e4, s2);
    cudaStreamWaitEvent(0, g_e3, 0);
    cudaStreamWaitEvent(0, g_e4, 0);

    // ---- phase 3: off -> sample on default ----
    off_mma_kernel<<<dim3(PP/128, NN), 256, OFF_SMEM>>>(w_off, b_off);
    sample_kernel<<<dim3(HH, NN*GG), 128>>>(cp, out);
}

// round 14
// speedup vs baseline: 1.0039x; 1.0039x over previous
#include <cuda_runtime.h>
#include <cuda_fp16.h>
#include <math.h>
#include <stdint.h>

// ---------------- problem constants ----------------
#define NN   8
#define CIN  256
#define C2   128
#define HH   128
#define WW   128
#define GG   8
#define PP   (HH*WW)      // 16384
#define HS   64
#define WS   64
#define PS   (HS*WS)      // 4096

// ---------------- scratch (device globals; no allocation) ----------------
__device__ __half g_tsp [NN*C2*PS];     // conv+bn(sp) at 64x64, fp16
__device__ __half g_cs  [NN*2*C2*PP];   // [cp1 | sp1] 256ch, fp16
__device__ __half g_cat [NN*192*PP];    // [redim(128) | fdir(32) | fdist(32)], fp16
__device__ float  g_sim [NN*GG*PP];
__device__ float  g_off [NN*32*PP];

// =====================================================================
// shared MMA helpers (1-term fp16: weights and inputs rounded once)
// =====================================================================
#define GEMM_SMEM 32768

__device__ __forceinline__ uint32_t smem_u32(const void* p) {
    uint32_t a;
    asm("{ .reg .u64 t; cvta.to.shared.u64 t, %1; cvt.u32.u64 %0, t; }"
        : "=r"(a) : "l"(p));
    return a;
}
__device__ __forceinline__ uint32_t pack2h(float a, float b) {
    return (uint32_t)__half_as_ushort(__float2half_rn(a))
         | ((uint32_t)__half_as_ushort(__float2half_rn(b)) << 16);
}
__device__ __forceinline__ void ldmx4(uint32_t* r, uint32_t addr) {
    asm volatile("ldmatrix.sync.aligned.m8n8.x4.shared.b16 {%0,%1,%2,%3}, [%4];"
                 : "=r"(r[0]), "=r"(r[1]), "=r"(r[2]), "=r"(r[3]) : "r"(addr));
}
__device__ __forceinline__ void ldmx4t(uint32_t* r, uint32_t addr) {
    asm volatile("ldmatrix.sync.aligned.m8n8.x4.trans.shared.b16 {%0,%1,%2,%3}, [%4];"
                 : "=r"(r[0]), "=r"(r[1]), "=r"(r[2]), "=r"(r[3]) : "r"(addr));
}
__device__ __forceinline__ void mma16816(float* c, const uint32_t* a, const uint32_t* b) {
    asm volatile("mma.sync.aligned.m16n8k16.row.col.f32.f16.f16.f32 "
                 "{%0,%1,%2,%3}, {%4,%5,%6,%7}, {%8,%9}, {%0,%1,%2,%3};"
                 : "+f"(c[0]), "+f"(c[1]), "+f"(c[2]), "+f"(c[3])
                 : "r"(a[0]), "r"(a[1]), "r"(a[2]), "r"(a[3]), "r"(b[0]), "r"(b[1]));
}
__device__ __forceinline__ uint32_t swzA(uint32_t bo) { return bo ^ (((bo >> 7) & 7) << 4); }
__device__ __forceinline__ uint32_t swzB(uint32_t bo) { return bo ^ (((bo >> 8) & 7) << 4); }

// =====================================================================
// 128-out 1x1 conv GEMM (1-term fp16), templated input/output dtype
// =====================================================================
template<typename TIN, typename TOUT>
__global__ void __launch_bounds__(256, 2) gemm_mma_kernel(
    const TIN* __restrict__ X, const float* __restrict__ Wm,
    const float* __restrict__ gscale, const float* __restrict__ bias,
    TOUT* __restrict__ Y, int Pn, long xns, long yns, int relu)
{
    extern __shared__ char smem[];
    char* ahs = smem;               // [128co][64k] fp16  16KB
    char* bhs = smem + 16384;       // [64k][128px] fp16  16KB

    const int t  = threadIdx.x;
    const int l  = t & 31, w = t >> 5;
    const int wm = w & 1, wn = w >> 1;
    const int n  = blockIdx.y, p0 = blockIdx.x * 128;
    const TIN* Xn = X + (long)n * xns;
    TOUT*      Yn = Y + (long)n * yns;

    const uint32_t ah0 = smem_u32(ahs);
    const uint32_t bh0 = smem_u32(bhs);

    float acc[4][4][4];
#pragma unroll
    for (int i = 0; i < 4; i++)
#pragma unroll
        for (int j = 0; j < 4; j++)
#pragma unroll
            for (int q = 0; q < 4; q++) acc[i][j][q] = 0.f;

    const int arow  = wm * 64 + (l & 15);
    const int akoff = (l >> 4) * 8;
    const int brow  = (l & 15);
    const int bnoff = wn * 32 + (l >> 4) * 8;

    for (int c = 0; c < 4; c++) {
        const int k0 = c * 64;
        __syncthreads();
        // ---- stage A (weights, fp16) ----
#pragma unroll
        for (int i = 0; i < 4; i++) {
            int idx = t + i * 256;
            int row = idx >> 3, ch = idx & 7;
            const float* wp = Wm + (long)row * 256 + k0 + ch * 8;
            float4 v0 = *(const float4*)wp;
            float4 v1 = *(const float4*)(wp + 4);
            uint4 h4;
            h4.x = pack2h(v0.x, v0.y);
            h4.y = pack2h(v0.z, v0.w);
            h4.z = pack2h(v1.x, v1.y);
            h4.w = pack2h(v1.z, v1.w);
            *(uint4*)(ahs + swzA(row * 128 + ch * 16)) = h4;
        }
        // ---- stage B (inputs, fp16) ----
#pragma unroll
        for (int i = 0; i < 4; i++) {
            int idx = t + i * 256;
            int k = idx >> 4, ch = idx & 15;
            if constexpr (sizeof(TIN) == 4) {
                const float* xp = (const float*)Xn + (long)(k0 + k) * Pn + p0 + ch * 8;
                float4 v0 = *(const float4*)xp;
                float4 v1 = *(const float4*)(xp + 4);
                uint4 h4;
                h4.x = pack2h(v0.x, v0.y);
                h4.y = pack2h(v0.z, v0.w);
                h4.z = pack2h(v1.x, v1.y);
                h4.w = pack2h(v1.z, v1.w);
                *(uint4*)(bhs + swzB(k * 256 + ch * 16)) = h4;
            } else {
                const __half* xp = (const __half*)Xn + (long)(k0 + k) * Pn + p0 + ch * 8;
                *(uint4*)(bhs + swzB(k * 256 + ch * 16)) = *(const uint4*)xp;
            }
        }
        __syncthreads();

#pragma unroll
        for (int ks = 0; ks < 4; ks++) {
            uint32_t a[4][4];
            uint32_t B[2][4];
#pragma unroll
            for (int i = 0; i < 4; i++) {
                uint32_t bo = (uint32_t)((arow + i * 16) * 128 + (akoff + ks * 16) * 2);
                ldmx4(a[i], ah0 + swzA(bo));
            }
#pragma unroll
            for (int j2 = 0; j2 < 2; j2++) {
                uint32_t bo = (uint32_t)((brow + ks * 16) * 256 + (bnoff + j2 * 16) * 2);
                ldmx4t(B[j2], bh0 + swzB(bo));
            }
#pragma unroll
            for (int i = 0; i < 4; i++)
#pragma unroll
                for (int j = 0; j < 4; j++)
                    mma16816(acc[i][j], a[i], &B[j >> 1][(j & 1) * 2]);
        }
    }

    const float bnfac = rsqrtf(1.f + 1e-5f);
    const int gid = l >> 2, tig = l & 3;
#pragma unroll
    for (int i = 0; i < 4; i++) {
        int co0 = wm * 64 + i * 16 + gid;
        int co1 = co0 + 8;
        float s0 = gscale ? gscale[co0] * bnfac : 1.f;
        float s1 = gscale ? gscale[co1] * bnfac : 1.f;
        float b0 = bias[co0], b1 = bias[co1];
#pragma unroll
        for (int j = 0; j < 4; j++) {
            int col = p0 + wn * 32 + j * 8 + 2 * tig;
            float2 r0, r1;
            r0.x = acc[i][j][0] * s0 + b0;
            r0.y = acc[i][j][1] * s0 + b0;
            r1.x = acc[i][j][2] * s1 + b1;
            r1.y = acc[i][j][3] * s1 + b1;
            if (relu) {
                r0.x = fmaxf(r0.x, 0.f); r0.y = fmaxf(r0.y, 0.f);
                r1.x = fmaxf(r1.x, 0.f); r1.y = fmaxf(r1.y, 0.f);
            }
            if constexpr (sizeof(TOUT) == 4) {
                *(float2*)((float*)Yn + (long)co0 * Pn + col) = r0;
                *(float2*)((float*)Yn + (long)co1 * Pn + col) = r1;
            } else {
                *(__half2*)((__half*)Yn + (long)co0 * Pn + col) = __floats2half2_rn(r0.x, r0.y);
                *(__half2*)((__half*)Yn + (long)co1 * Pn + col) = __floats2half2_rn(r1.x, r1.y);
            }
        }
    }
}

// =====================================================================
// fdist: 3x3 conv 128->32 on |cp1-sp1| (fp16) as HMMA implicit GEMM (1-term)
// =====================================================================
#define FDB_H   28160      // [3][130][36] ushort
#define FDA_H   18944      // [32][296] ushort
#define FD_SMEM (FDB_H + FDA_H)   // 47104

__global__ void __launch_bounds__(256, 2) fdist_mma_kernel(
    const float* __restrict__ wD, const float* __restrict__ bD)
{
    extern __shared__ char smem[];
    ushort* Bh = (ushort*)smem;
    ushort* Ah = (ushort*)(smem + FDB_H);

    const int t = threadIdx.x, l = t & 31, w = t >> 5;
    const int y = blockIdx.x, n = blockIdx.y;
    const int n0 = w * 16;
    const __half* csn = g_cs + (long)n * (2*C2*PP);

    float acc[2][2][4];
#pragma unroll
    for (int m = 0; m < 2; m++)
#pragma unroll
        for (int j = 0; j < 2; j++)
#pragma unroll
            for (int q = 0; q < 4; q++) acc[m][j][q] = 0.f;

    const uint32_t ah0 = smem_u32(Ah);

    for (int c0 = 0; c0 < C2; c0 += 32) {
        __syncthreads();
        if (t < 96) {
            int r = t >> 5, c = t & 31;
            Bh[(r * 130 + 0)   * 36 + c] = 0;
            Bh[(r * 130 + 129) * 36 + c] = 0;
        }
        for (int i = t; i < 3072; i += 256) {
            int r = i >> 10;
            int c = (i >> 5) & 31;
            int q = i & 31;
            int ys = y + r - 1;
            int px = q * 4;
            int ib = (r * 130 + 1 + px) * 36 + c;
            if (ys >= 0 && ys < HH) {
                long off = (long)(c0 + c) * PP + ys * WW + px;
                __half2 a0 = *(const __half2*)(csn + off);
                __half2 a1 = *(const __half2*)(csn + off + 2);
                __half2 b0 = *(const __half2*)(csn + off + (long)C2 * PP);
                __half2 b1 = *(const __half2*)(csn + off + (long)C2 * PP + 2);
                __half2 d0 = __habs2(__hsub2(a0, b0));
                __half2 d1 = __habs2(__hsub2(a1, b1));
                Bh[ib]       = __half_as_ushort(__low2half(d0));
                Bh[ib + 36]  = __half_as_ushort(__high2half(d0));
                Bh[ib + 72]  = __half_as_ushort(__low2half(d1));
                Bh[ib + 108] = __half_as_ushort(__high2half(d1));
            } else {
                Bh[ib] = 0; Bh[ib + 36] = 0; Bh[ib + 72] = 0; Bh[ib + 108] = 0;
            }
        }
        for (int i = t; i < 32 * 288; i += 256) {
            int co = i / 288, kp = i % 288;
            int tap = kp >> 5, cl = kp & 31;
            Ah[co * 296 + kp] =
                __half_as_ushort(__float2half_rn(wD[co * 1152 + (c0 + cl) * 9 + tap]));
        }
        __syncthreads();

#pragma unroll
        for (int tap = 0; tap < 9; tap++) {
            const int dy = tap / 3, dx = tap % 3;
#pragma unroll
            for (int ks = 0; ks < 2; ks++) {
                uint32_t ahf[2][4];
#pragma unroll
                for (int m = 0; m < 2; m++) {
                    uint32_t ao = (uint32_t)((m * 16 + (l & 15)) * 296
                                  + tap * 32 + ks * 16 + (l >> 4) * 8) * 2;
                    ldmx4(ahf[m], ah0 + ao);
                }
                uint32_t bhf[2][2];
#pragma unroll
                for (int j2 = 0; j2 < 2; j2++) {
                    int px = n0 + j2 * 8 + (l >> 2) + dx;
                    int c  = ks * 16 + (l & 3) * 2;
                    int ib = (dy * 130 + px) * 36 + c;
                    bhf[j2][0] = *(const uint32_t*)&Bh[ib];
                    bhf[j2][1] = *(const uint32_t*)&Bh[ib + 8];
                }
#pragma unroll
                for (int m = 0; m < 2; m++)
#pragma unroll
                    for (int j2 = 0; j2 < 2; j2++)
                        mma16816(acc[m][j2], ahf[m], bhf[j2]);
            }
        }
    }

    __half* outp = g_cat + (long)n * (192 * PP) + (long)160 * PP + y * WW;
#pragma unroll
    for (int m = 0; m < 2; m++) {
        int co = m * 16 + (l >> 2);
        float b0 = bD[co], b1 = bD[co + 8];
#pragma unroll
        for (int j2 = 0; j2 < 2; j2++) {
            int px = n0 + j2 * 8 + (l & 3) * 2;
            *(__half2*)(outp + (long)co * PP + px) =
                __floats2half2_rn(acc[m][j2][0] + b0, acc[m][j2][1] + b0);
            *(__half2*)(outp + (long)(co + 8) * PP + px) =
                __floats2half2_rn(acc[m][j2][2] + b1, acc[m][j2][3] + b1);
        }
    }
}

// =====================================================================
// fdir: 3x3 conv 8->32 on sim as HMMA implicit GEMM (1-term)
// =====================================================================
__global__ void __launch_bounds__(256, 2) fdir_mma_kernel(
    const float* __restrict__ wd, const float* __restrict__ bd)
{
    __shared__ ushort Bs[3 * 130 * 8];   // [row][halo px][ch]
    __shared__ ushort Ah[32 * 88];

    const int t = threadIdx.x, l = t & 31, w = t >> 5;
    const int y = blockIdx.x, n = blockIdx.y;
    const int n0 = w * 16;
    const float* simn = g_sim + (long)n * GG * PP;

    for (int i = t; i < 32 * 88; i += 256) {
        int co = i / 88, kp = i % 88;
        ushort h = 0;
        if (kp < 72) {
            int tap = kp >> 3, c = kp & 7;
            h = __half_as_ushort(__float2half_rn(wd[co * 72 + c * 9 + tap]));
        }
        Ah[i] = h;
    }
    if (t < 48) {
        int r = t >> 4, side = (t >> 3) & 1, c = t & 7;
        Bs[(r * 130 + (side ? 129 : 0)) * 8 + c] = 0;
    }
    for (int i = t; i < 1536; i += 256) {
        int r = i >> 9;
        int c = (i >> 6) & 7;
        int q = i & 63;
        int px = q * 2;
        int ys = y + r - 1;
        int ib = (r * 130 + 1 + px) * 8 + c;
        if (ys >= 0 && ys < HH) {
            float2 v = *(const float2*)(simn + (long)c * PP + ys * WW + px);
            Bs[ib]     = __half_as_ushort(__float2half_rn(v.x));
            Bs[ib + 8] = __half_as_ushort(__float2half_rn(v.y));
        } else {
            Bs[ib] = 0; Bs[ib + 8] = 0;
        }
    }
    __syncthreads();

    const uint32_t ah0 = smem_u32(Ah);

    float acc[2][2][4];
#pragma unroll
    for (int m = 0; m < 2; m++)
#pragma unroll
        for (int j = 0; j < 2; j++)
#pragma unroll
            for (int q = 0; q < 4; q++) acc[m][j][q] = 0.f;

    const int cfrag = (l & 3) * 2;
#pragma unroll
    for (int ks = 0; ks < 5; ks++) {
        uint32_t ahf[2][4];
#pragma unroll
        for (int m = 0; m < 2; m++) {
            uint32_t ao = (uint32_t)((m * 16 + (l & 15)) * 88 + ks * 16 + (l >> 4) * 8) * 2;
            ldmx4(ahf[m], ah0 + ao);
        }
        const int tap_a = 2 * ks, tap_b = 2 * ks + 1;
        const int dya = tap_a / 3, dxa = tap_a % 3;
        const int dyb = tap_b / 3, dxb = tap_b % 3;
        uint32_t bhf[2][2];
#pragma unroll
        for (int j2 = 0; j2 < 2; j2++) {
            int pxb = n0 + j2 * 8 + (l >> 2);
            bhf[j2][0] = *(const uint32_t*)&Bs[((dya * 130) + pxb + dxa) * 8 + cfrag];
            bhf[j2][1] = (tap_b < 9)
                ? *(const uint32_t*)&Bs[((dyb * 130) + pxb + dxb) * 8 + cfrag]
                : 0u;
        }
#pragma unroll
        for (int m = 0; m < 2; m++)
#pragma unroll
            for (int j2 = 0; j2 < 2; j2++)
                mma16816(acc[m][j2], ahf[m], bhf[j2]);
    }

    __half* outp = g_cat + (long)n * (192 * PP) + (long)128 * PP + y * WW;
#pragma unroll
    for (int m = 0; m < 2; m++) {
        int co = m * 16 + (l >> 2);
        float b0 = bd[co], b1 = bd[co + 8];
#pragma unroll
        for (int j2 = 0; j2 < 2; j2++) {
            int px = n0 + j2 * 8 + (l & 3) * 2;
            *(__half2*)(outp + (long)co * PP + px) =
                __floats2half2_rn(acc[m][j2][0] + b0, acc[m][j2][1] + b0);
            *(__half2*)(outp + (long)(co + 8) * PP + px) =
                __floats2half2_rn(acc[m][j2][2] + b1, acc[m][j2][3] + b1);
        }
    }
}

// =====================================================================
// off: 1x1 conv 192->32 as HMMA GEMM (1-term, fp16 input from g_cat)
// =====================================================================
#define OFA_H 12800          // [32][200] ushort
#define OFB_H 16384          // [64][128px] ushort
#define OFF_SMEM (OFA_H + OFB_H)   // 29184

__global__ void __launch_bounds__(256, 2) off_mma_kernel(
    const float* __restrict__ wo, const float* __restrict__ bo)
{
    extern __shared__ char smem[];
    ushort* Ah = (ushort*)smem;
    char*   bhs = smem + OFA_H;

    const int t = threadIdx.x, l = t & 31, w = t >> 5;
    const int n = blockIdx.y, p0 = blockIdx.x * 128;
    const __half* xn = g_cat + (long)n * (192 * PP);

    for (int i = t; i < 32 * 192; i += 256) {
        int co = i / 192, k = i % 192;
        Ah[co * 200 + k] = __half_as_ushort(__float2half_rn(wo[co * 192 + k]));
    }

    float acc[2][2][4];
#pragma unroll
    for (int m = 0; m < 2; m++)
#pragma unroll
        for (int j = 0; j < 2; j++)
#pragma unroll
            for (int q = 0; q < 4; q++) acc[m][j][q] = 0.f;

    const uint32_t ah0 = smem_u32(Ah);
    const uint32_t bh0 = smem_u32(bhs);
    const int brow  = l & 15;
    const int bnoff = w * 16 + (l >> 4) * 8;

    for (int kc = 0; kc < 3; kc++) {
        const int k0 = kc * 64;
        __syncthreads();
#pragma unroll
        for (int i = 0; i < 4; i++) {
            int idx = t + i * 256;
            int k = idx >> 4, ch = idx & 15;
            const __half* xp = xn + (long)(k0 + k) * PP + p0 + ch * 8;
            *(uint4*)(bhs + swzB(k * 256 + ch * 16)) = *(const uint4*)xp;
        }
        __syncthreads();

#pragma unroll
        for (int ks = 0; ks < 4; ks++) {
            uint32_t ahf[2][4];
#pragma unroll
            for (int m = 0; m < 2; m++) {
                uint32_t ao = (uint32_t)((m * 16 + (l & 15)) * 200
                              + k0 + ks * 16 + (l >> 4) * 8) * 2;
                ldmx4(ahf[m], ah0 + ao);
            }
            uint32_t Bhf[4];
            ldmx4t(Bhf, bh0 + swzB((uint32_t)((brow + ks * 16) * 256 + bnoff * 2)));
#pragma unroll
            for (int m = 0; m < 2; m++)
#pragma unroll
                for (int j2 = 0; j2 < 2; j2++)
                    mma16816(acc[m][j2], ahf[m], &Bhf[j2 * 2]);
        }
    }

    float* outp = g_off + (long)n * (32 * PP) + p0;
#pragma unroll
    for (int m = 0; m < 2; m++) {
        int co = m * 16 + (l >> 2);
        float b0 = bo[co], b1 = bo[co + 8];
#pragma unroll
        for (int j2 = 0; j2 < 2; j2++) {
            int px = w * 16 + j2 * 8 + (l & 3) * 2;
            outp[(long)co * PP + px]           = acc[m][j2][0] + b0;
            outp[(long)co * PP + px + 1]       = acc[m][j2][1] + b0;
            outp[(long)(co + 8) * PP + px]     = acc[m][j2][2] + b1;
            outp[(long)(co + 8) * PP + px + 1] = acc[m][j2][3] + b1;
        }
    }
}

// ---------------- upsample conv+bn(sp) (fp16), relu, into g_cs[128:] ----------------
__global__ void __launch_bounds__(256) up_relu_kernel()
{
    long gid = (long)blockIdx.x * 256 + threadIdx.x;
    int x = gid & 127;
    int y = (gid >> 7) & 127;
    int c = (int)((gid >> 14) & 127);
    int n = (int)(gid >> 21);
    float ysf = y * (63.f / 127.f);
    int y0 = (int)ysf; float wy = ysf - y0; int y1 = min(y0 + 1, 63);
    float xsf = x * (63.f / 127.f);
    int x0 = (int)xsf; float wx = xsf - x0; int x1 = min(x0 + 1, 63);
    const __half* b = g_tsp + ((long)n * C2 + c) * PS;
    float v = (__half2float(b[y0*WS + x0]) * (1.f - wx) + __half2float(b[y0*WS + x1]) * wx) * (1.f - wy)
            + (__half2float(b[y1*WS + x0]) * (1.f - wx) + __half2float(b[y1*WS + x1]) * wx) * wy;
    g_cs[(long)n * (2*C2*PP) + (long)(C2 + c) * PP + (y * WW + x)] =
        __float2half_rn(fmaxf(v, 0.f));
}

// ---------------- group cosine similarity (fp16 inputs, 2 px/thread) ----------------
__global__ void __launch_bounds__(256) sim_kernel()
{
    long gid = (long)blockIdx.x * 256 + threadIdx.x;  // over NN*GG*PP/2
    int p2 = (int)(gid & (PP/2 - 1));
    int g  = (int)((gid >> 13) & 7);
    int n  = (int)(gid >> 16);
    const __half* a = g_cs + (long)n * (2*C2*PP) + (long)(g * 16) * PP + 2 * p2;
    const __half* b = a + (long)C2 * PP;
    float2 num = {0.f, 0.f}, na = {0.f, 0.f}, nb = {0.f, 0.f};
#pragma unroll
    for (int cc = 0; cc < 16; cc++) {
        float2 af = __half22float2(*(const __half2*)(a + (long)cc * PP));
        float2 bf = __half22float2(*(const __half2*)(b + (long)cc * PP));
        num.x += af.x * bf.x; num.y += af.y * bf.y;
        na.x  += af.x * af.x; na.y  += af.y * af.y;
        nb.x  += bf.x * bf.x; nb.y  += bf.y * bf.y;
    }
    float2 s;
    s.x = num.x / (fmaxf(sqrtf(na.x), 1e-8f) * fmaxf(sqrtf(nb.x), 1e-8f));
    s.y = num.y / (fmaxf(sqrtf(na.y), 1e-8f) * fmaxf(sqrtf(nb.y), 1e-8f));
    *(float2*)(g_sim + gid * 2) = s;
}

// ---------------- final: dual grid_sample + add (sp upsample fused, 3x3 stencil) ----------------
__device__ __forceinline__ void make_taps(int x, int y, float ox, float oy,
                                          int* tx, int* ty, float* wgt)
{
    float gx = x * (2.f / 127.f) - 1.f + ox * (1.f / 128.f);
    float gy = y * (2.f / 127.f) - 1.f + oy * (1.f / 128.f);
    float px = (gx + 1.f) * 0.5f * 127.f;
    float py = (gy + 1.f) * 0.5f * 127.f;
    float x0f = floorf(px), y0f = floorf(py);
    float wx = px - x0f, wy = py - y0f;
    int x0 = (int)x0f, y0 = (int)y0f, x1 = x0 + 1, y1 = y0 + 1;
    bool vx0 = (x0 >= 0) && (x0 <= 127), vx1 = (x1 >= 0) && (x1 <= 127);
    bool vy0 = (y0 >= 0) && (y0 <= 127), vy1 = (y1 >= 0) && (y1 <= 127);
    int cx0 = min(max(x0, 0), 127), cx1 = min(max(x1, 0), 127);
    int cy0 = min(max(y0, 0), 127), cy1 = min(max(y1, 0), 127);
    tx[0] = cx0; ty[0] = cy0; wgt[0] = (vx0 && vy0) ? (1.f - wx) * (1.f - wy) : 0.f;
    tx[1] = cx1; ty[1] = cy0; wgt[1] = (vx1 && vy0) ? wx * (1.f - wy) : 0.f;
    tx[2] = cx0; ty[2] = cy1; wgt[2] = (vx0 && vy1) ? (1.f - wx) * wy : 0.f;
    tx[3] = cx1; ty[3] = cy1; wgt[3] = (vx1 && vy1) ? wx * wy : 0.f;
}

__global__ void __launch_bounds__(256) sample_kernel(const float* __restrict__ cp,
                                                     const float* __restrict__ sp,
                                                     float* __restrict__ out)
{
    int x    = threadIdx.x;      // 0..127
    int half = threadIdx.y;      // 0..1 (channel split)
    int y    = blockIdx.x;
    int ng   = blockIdx.y;
    int n    = ng >> 3, gi = ng & 7;
    int p    = (y << 7) | x;
    const float* offn = g_off + (long)n * (32*PP) + p;
    float olx = offn[(long)(2*gi)      * PP];
    float oly = offn[(long)(2*gi + 1)  * PP];
    float ohx = offn[(long)(16 + 2*gi) * PP];
    float ohy = offn[(long)(17 + 2*gi) * PP];

    int lx[4], ly[4], hx[4], hy[4];
    float wl[4], wh[4];
    make_taps(x, y, olx, oly, lx, ly, wl);
    make_taps(x, y, ohx, ohy, hx, hy, wh);

    int il[4];
#pragma unroll
    for (int k = 0; k < 4; k++) il[k] = ly[k] * WW + lx[k];

    // Each fine sp tap expands to 4 coarse taps; all 16 lie in a 3x3 coarse
    // window (coarse map slope 63/127 < 1). Accumulate weights into ws[3][3].
    int cx0[4], cy0[4], cx1[4], cy1[4];
    float cwx[4], cwy[4];
    int xmin = 64, ymin = 64;
#pragma unroll
    for (int k = 0; k < 4; k++) {
        float ysf = hy[k] * (63.f / 127.f);
        int y0 = (int)ysf; cwy[k] = ysf - y0;
        cy0[k] = y0; cy1[k] = min(y0 + 1, 63);
        float xsf = hx[k] * (63.f / 127.f);
        int x0 = (int)xsf; cwx[k] = xsf - x0;
        cx0[k] = x0; cx1[k] = min(x0 + 1, 63);
        ymin = min(ymin, y0); xmin = min(xmin, x0);
    }
    float ws[9];
#pragma unroll
    for (int i = 0; i < 9; i++) ws[i] = 0.f;
#pragma unroll
    for (int k = 0; k < 4; k++) {
        float wk = wh[k];
        int r0 = cy0[k] - ymin, r1 = cy1[k] - ymin;
        int c0 = cx0[k] - xmin, c1 = cx1[k] - xmin;
        float wx = cwx[k], wy = cwy[k];
        ws[r0*3 + c0] += wk * (1.f - wx) * (1.f - wy);
        ws[r0*3 + c1] += wk * wx * (1.f - wy);
        ws[r1*3 + c0] += wk * (1.f - wx) * wy;
        ws[r1*3 + c1] += wk * wx * wy;
    }
    int si[9];
#pragma unroll
    for (int r = 0; r < 3; r++)
#pragma unroll
        for (int c = 0; c < 3; c++) {
            int yy = min(ymin + r, 63);     // clamp address; zero-weight slots only
            int xx = min(xmin + c, 63);
            si[r*3 + c] = yy * WS + xx;
        }

    long cb_cp = ((long)n * CIN + gi * 32) * PP;
    long cb_sp = ((long)n * CIN + gi * 32) * PS;
    const float* cpp = cp + cb_cp;
    const float* spp = sp + cb_sp;
    float* op = out + cb_cp + p;
    const int cbeg = half * 16;
#pragma unroll 2
    for (int c = cbeg; c < cbeg + 16; c++) {
        const float* a = cpp + (long)c * PP;
        const float* s = spp + (long)c * PS;
        float v = wl[0]*a[il[0]] + wl[1]*a[il[1]] + wl[2]*a[il[2]] + wl[3]*a[il[3]];
#pragma unroll
        for (int i = 0; i < 9; i++) v += ws[i] * s[si[i]];
        op[(long)c * PP] = v;
    }
}

// ---------------- persistent host-side stream/event handles ----------------
static cudaStream_t g_s1 = nullptr, g_s2 = nullptr;
static cudaEvent_t  g_e0, g_e1, g_e2, g_e3, g_e4;
static bool g_init_done = false;

// ---------------- launch (fork/join stream overlap, capture-safe) ----------------
extern "C" void kernel_launch(void* const* d_in, const int* in_sizes, int n_in,
                              void* d_out, int out_size)
{
    const float* cp      = (const float*)d_in[0];
    const float* sp      = (const float*)d_in[1];
    const float* w_cp    = (const float*)d_in[2];
    const float* gb_cp   = (const float*)d_in[3];
    const float* b_cp    = (const float*)d_in[4];
    const float* w_sp    = (const float*)d_in[5];
    const float* gb_sp   = (const float*)d_in[6];
    const float* b_sp    = (const float*)d_in[7];
    const float* w_redim = (const float*)d_in[8];
    const float* b_redim = (const float*)d_in[9];
    const float* w_dir   = (const float*)d_in[10];
    const float* b_dir   = (const float*)d_in[11];
    const float* w_dist  = (const float*)d_in[12];
    const float* b_dist  = (const float*)d_in[13];
    const float* w_off   = (const float*)d_in[14];
    const float* b_off   = (const float*)d_in[15];
    float* out = (float*)d_out;

    __half *p_tsp, *p_cs, *p_cat;
    cudaGetSymbolAddress((void**)&p_tsp, g_tsp);
    cudaGetSymbolAddress((void**)&p_cs,  g_cs);
    cudaGetSymbolAddress((void**)&p_cat, g_cat);

    if (!g_init_done) {
        cudaStreamCreateWithFlags(&g_s1, cudaStreamNonBlocking);
        cudaStreamCreateWithFlags(&g_s2, cudaStreamNonBlocking);
        cudaEventCreateWithFlags(&g_e0, cudaEventDisableTiming);
        cudaEventCreateWithFlags(&g_e1, cudaEventDisableTiming);
        cudaEventCreateWithFlags(&g_e2, cudaEventDisableTiming);
        cudaEventCreateWithFlags(&g_e3, cudaEventDisableTiming);
        cudaEventCreateWithFlags(&g_e4, cudaEventDisableTiming);
        cudaFuncSetAttribute(gemm_mma_kernel<float, __half>,
                             cudaFuncAttributeMaxDynamicSharedMemorySize, GEMM_SMEM);
        cudaFuncSetAttribute(gemm_mma_kernel<__half, __half>,
                             cudaFuncAttributeMaxDynamicSharedMemorySize, GEMM_SMEM);
        cudaFuncSetAttribute(fdist_mma_kernel,
                             cudaFuncAttributeMaxDynamicSharedMemorySize, FD_SMEM);
        cudaFuncSetAttribute(off_mma_kernel,
                             cudaFuncAttributeMaxDynamicSharedMemorySize, OFF_SMEM);
        g_init_done = true;
    }
    cudaStream_t s1 = g_s1, s2 = g_s2;

    // ---- phase 1: {sp-gemm -> up_relu} on s1  ||  {cp-gemm} on default ----
    cudaEventRecord(g_e0, 0);
    cudaStreamWaitEvent(s1, g_e0, 0);

    gemm_mma_kernel<float, __half><<<dim3(PS/128, NN), 256, GEMM_SMEM, s1>>>(
        sp, w_sp, gb_sp, b_sp, p_tsp, PS, (long)CIN*PS, (long)C2*PS, 0);
    up_relu_kernel<<<NN*C2*PP/256, 256, 0, s1>>>();

    gemm_mma_kernel<float, __half><<<dim3(PP/128, NN), 256, GEMM_SMEM>>>(
        cp, w_cp, gb_cp, b_cp, p_cs, PP, (long)CIN*PP, (long)2*C2*PP, 1);

    cudaEventRecord(g_e1, s1);
    cudaStreamWaitEvent(0, g_e1, 0);

    // ---- phase 2: {redim} on default || {sim -> fdir} on s1 || {fdist} on s2 ----
    cudaEventRecord(g_e2, 0);
    cudaStreamWaitEvent(s1, g_e2, 0);
    cudaStreamWaitEvent(s2, g_e2, 0);

    gemm_mma_kernel<__half, __half><<<dim3(PP/128, NN), 256, GEMM_SMEM>>>(
        p_cs, w_redim, nullptr, b_redim, p_cat, PP, (long)2*C2*PP, (long)192*PP, 0);

    sim_kernel<<<NN*GG*(PP/2)/256, 256, 0, s1>>>();
    fdir_mma_kernel<<<dim3(HH, NN), 256, 0, s1>>>(w_dir, b_dir);

    fdist_mma_kernel<<<dim3(HH, NN), 256, FD_SMEM, s2>>>(w_dist, b_dist);

    cudaEventRecord(g_e3, s1);
    cudaEventRecord(g_e4, s2);
    cudaStreamWaitEvent(0, g_e3, 0);
    cudaStreamWaitEvent(0, g_e4, 0);

    // ---- phase 3: off -> sample on default ----
    off_mma_kernel<<<dim3(PP/128, NN), 256, OFF_SMEM>>>(w_off, b_off);
    sample_kernel<<<dim3(HH, NN*GG), dim3(128, 2)>>>(cp, sp, out);
}

// round 15
// speedup vs baseline: 1.0118x; 1.0079x over previous
#include <cuda_runtime.h>
#include <cuda_fp16.h>
#include <math.h>
#include <stdint.h>

// ---------------- problem constants ----------------
#define NN   8
#define CIN  256
#define C2   128
#define HH   128
#define WW   128
#define GG   8
#define PP   (HH*WW)      // 16384
#define HS   64
#define WS   64
#define PS   (HS*WS)      // 4096

// ---------------- scratch (device globals; no allocation) ----------------
__device__ __half g_tsp [NN*C2*PS];     // conv+bn(sp) at 64x64, fp16
__device__ __half g_cs  [NN*2*C2*PP];   // [cp1 | sp1] 256ch, fp16
__device__ __half g_cat [NN*192*PP];    // [redim(128) | fdir(32) | fdist(32)], fp16
__device__ float  g_sim [NN*GG*PP];
__device__ float  g_off [NN*32*PP];

// =====================================================================
// shared MMA helpers (1-term fp16: weights and inputs rounded once)
// =====================================================================
#define GEMM_SMEM 32768

__device__ __forceinline__ uint32_t smem_u32(const void* p) {
    uint32_t a;
    asm("{ .reg .u64 t; cvta.to.shared.u64 t, %1; cvt.u32.u64 %0, t; }"
        : "=r"(a) : "l"(p));
    return a;
}
__device__ __forceinline__ uint32_t pack2h(float a, float b) {
    return (uint32_t)__half_as_ushort(__float2half_rn(a))
         | ((uint32_t)__half_as_ushort(__float2half_rn(b)) << 16);
}
__device__ __forceinline__ void ldmx4(uint32_t* r, uint32_t addr) {
    asm volatile("ldmatrix.sync.aligned.m8n8.x4.shared.b16 {%0,%1,%2,%3}, [%4];"
                 : "=r"(r[0]), "=r"(r[1]), "=r"(r[2]), "=r"(r[3]) : "r"(addr));
}
__device__ __forceinline__ void ldmx4t(uint32_t* r, uint32_t addr) {
    asm volatile("ldmatrix.sync.aligned.m8n8.x4.trans.shared.b16 {%0,%1,%2,%3}, [%4];"
                 : "=r"(r[0]), "=r"(r[1]), "=r"(r[2]), "=r"(r[3]) : "r"(addr));
}
__device__ __forceinline__ void mma16816(float* c, const uint32_t* a, const uint32_t* b) {
    asm volatile("mma.sync.aligned.m16n8k16.row.col.f32.f16.f16.f32 "
                 "{%0,%1,%2,%3}, {%4,%5,%6,%7}, {%8,%9}, {%0,%1,%2,%3};"
                 : "+f"(c[0]), "+f"(c[1]), "+f"(c[2]), "+f"(c[3])
                 : "r"(a[0]), "r"(a[1]), "r"(a[2]), "r"(a[3]), "r"(b[0]), "r"(b[1]));
}
__device__ __forceinline__ uint32_t swzA(uint32_t bo) { return bo ^ (((bo >> 7) & 7) << 4); }
__device__ __forceinline__ uint32_t swzB(uint32_t bo) { return bo ^ (((bo >> 8) & 7) << 4); }

// =====================================================================
// 128-out 1x1 conv GEMM (1-term fp16), templated input/output dtype
// =====================================================================
template<typename TIN, typename TOUT>
__global__ void __launch_bounds__(256, 2) gemm_mma_kernel(
    const TIN* __restrict__ X, const float* __restrict__ Wm,
    const float* __restrict__ gscale, const float* __restrict__ bias,
    TOUT* __restrict__ Y, int Pn, long xns, long yns, int relu)
{
    extern __shared__ char smem[];
    char* ahs = smem;               // [128co][64k] fp16  16KB
    char* bhs = smem + 16384;       // [64k][128px] fp16  16KB

    const int t  = threadIdx.x;
    const int l  = t & 31, w = t >> 5;
    const int wm = w & 1, wn = w >> 1;
    const int n  = blockIdx.y, p0 = blockIdx.x * 128;
    const TIN* Xn = X + (long)n * xns;
    TOUT*      Yn = Y + (long)n * yns;

    const uint32_t ah0 = smem_u32(ahs);
    const uint32_t bh0 = smem_u32(bhs);

    float acc[4][4][4];
#pragma unroll
    for (int i = 0; i < 4; i++)
#pragma unroll
        for (int j = 0; j < 4; j++)
#pragma unroll
            for (int q = 0; q < 4; q++) acc[i][j][q] = 0.f;

    const int arow  = wm * 64 + (l & 15);
    const int akoff = (l >> 4) * 8;
    const int brow  = (l & 15);
    const int bnoff = wn * 32 + (l >> 4) * 8;

    for (int c = 0; c < 4; c++) {
        const int k0 = c * 64;
        __syncthreads();
        // ---- stage A (weights, fp16) ----
#pragma unroll
        for (int i = 0; i < 4; i++) {
            int idx = t + i * 256;
            int row = idx >> 3, ch = idx & 7;
            const float* wp = Wm + (long)row * 256 + k0 + ch * 8;
            float4 v0 = *(const float4*)wp;
            float4 v1 = *(const float4*)(wp + 4);
            uint4 h4;
            h4.x = pack2h(v0.x, v0.y);
            h4.y = pack2h(v0.z, v0.w);
            h4.z = pack2h(v1.x, v1.y);
            h4.w = pack2h(v1.z, v1.w);
            *(uint4*)(ahs + swzA(row * 128 + ch * 16)) = h4;
        }
        // ---- stage B (inputs, fp16) ----
#pragma unroll
        for (int i = 0; i < 4; i++) {
            int idx = t + i * 256;
            int k = idx >> 4, ch = idx & 15;
            if constexpr (sizeof(TIN) == 4) {
                const float* xp = (const float*)Xn + (long)(k0 + k) * Pn + p0 + ch * 8;
                float4 v0 = *(const float4*)xp;
                float4 v1 = *(const float4*)(xp + 4);
                uint4 h4;
                h4.x = pack2h(v0.x, v0.y);
                h4.y = pack2h(v0.z, v0.w);
                h4.z = pack2h(v1.x, v1.y);
                h4.w = pack2h(v1.z, v1.w);
                *(uint4*)(bhs + swzB(k * 256 + ch * 16)) = h4;
            } else {
                const __half* xp = (const __half*)Xn + (long)(k0 + k) * Pn + p0 + ch * 8;
                *(uint4*)(bhs + swzB(k * 256 + ch * 16)) = *(const uint4*)xp;
            }
        }
        __syncthreads();

#pragma unroll
        for (int ks = 0; ks < 4; ks++) {
            uint32_t a[4][4];
            uint32_t B[2][4];
#pragma unroll
            for (int i = 0; i < 4; i++) {
                uint32_t bo = (uint32_t)((arow + i * 16) * 128 + (akoff + ks * 16) * 2);
                ldmx4(a[i], ah0 + swzA(bo));
            }
#pragma unroll
            for (int j2 = 0; j2 < 2; j2++) {
                uint32_t bo = (uint32_t)((brow + ks * 16) * 256 + (bnoff + j2 * 16) * 2);
                ldmx4t(B[j2], bh0 + swzB(bo));
            }
#pragma unroll
            for (int i = 0; i < 4; i++)
#pragma unroll
                for (int j = 0; j < 4; j++)
                    mma16816(acc[i][j], a[i], &B[j >> 1][(j & 1) * 2]);
        }
    }

    const float bnfac = rsqrtf(1.f + 1e-5f);
    const int gid = l >> 2, tig = l & 3;
#pragma unroll
    for (int i = 0; i < 4; i++) {
        int co0 = wm * 64 + i * 16 + gid;
        int co1 = co0 + 8;
        float s0 = gscale ? gscale[co0] * bnfac : 1.f;
        float s1 = gscale ? gscale[co1] * bnfac : 1.f;
        float b0 = bias[co0], b1 = bias[co1];
#pragma unroll
        for (int j = 0; j < 4; j++) {
            int col = p0 + wn * 32 + j * 8 + 2 * tig;
            float2 r0, r1;
            r0.x = acc[i][j][0] * s0 + b0;
            r0.y = acc[i][j][1] * s0 + b0;
            r1.x = acc[i][j][2] * s1 + b1;
            r1.y = acc[i][j][3] * s1 + b1;
            if (relu) {
                r0.x = fmaxf(r0.x, 0.f); r0.y = fmaxf(r0.y, 0.f);
                r1.x = fmaxf(r1.x, 0.f); r1.y = fmaxf(r1.y, 0.f);
            }
            if constexpr (sizeof(TOUT) == 4) {
                *(float2*)((float*)Yn + (long)co0 * Pn + col) = r0;
                *(float2*)((float*)Yn + (long)co1 * Pn + col) = r1;
            } else {
                *(__half2*)((__half*)Yn + (long)co0 * Pn + col) = __floats2half2_rn(r0.x, r0.y);
                *(__half2*)((__half*)Yn + (long)co1 * Pn + col) = __floats2half2_rn(r1.x, r1.y);
            }
        }
    }
}

// =====================================================================
// fdist: 3x3 conv 128->32 on |cp1-sp1| (fp16) as HMMA implicit GEMM (1-term)
// =====================================================================
#define FDB_H   28160      // [3][130][36] ushort
#define FDA_H   18944      // [32][296] ushort
#define FD_SMEM (FDB_H + FDA_H)   // 47104

__global__ void __launch_bounds__(256, 2) fdist_mma_kernel(
    const float* __restrict__ wD, const float* __restrict__ bD)
{
    extern __shared__ char smem[];
    ushort* Bh = (ushort*)smem;
    ushort* Ah = (ushort*)(smem + FDB_H);

    const int t = threadIdx.x, l = t & 31, w = t >> 5;
    const int y = blockIdx.x, n = blockIdx.y;
    const int n0 = w * 16;
    const __half* csn = g_cs + (long)n * (2*C2*PP);

    float acc[2][2][4];
#pragma unroll
    for (int m = 0; m < 2; m++)
#pragma unroll
        for (int j = 0; j < 2; j++)
#pragma unroll
            for (int q = 0; q < 4; q++) acc[m][j][q] = 0.f;

    const uint32_t ah0 = smem_u32(Ah);

    for (int c0 = 0; c0 < C2; c0 += 32) {
        __syncthreads();
        if (t < 96) {
            int r = t >> 5, c = t & 31;
            Bh[(r * 130 + 0)   * 36 + c] = 0;
            Bh[(r * 130 + 129) * 36 + c] = 0;
        }
        for (int i = t; i < 3072; i += 256) {
            int r = i >> 10;
            int c = (i >> 5) & 31;
            int q = i & 31;
            int ys = y + r - 1;
            int px = q * 4;
            int ib = (r * 130 + 1 + px) * 36 + c;
            if (ys >= 0 && ys < HH) {
                long off = (long)(c0 + c) * PP + ys * WW + px;
                __half2 a0 = *(const __half2*)(csn + off);
                __half2 a1 = *(const __half2*)(csn + off + 2);
                __half2 b0 = *(const __half2*)(csn + off + (long)C2 * PP);
                __half2 b1 = *(const __half2*)(csn + off + (long)C2 * PP + 2);
                __half2 d0 = __habs2(__hsub2(a0, b0));
                __half2 d1 = __habs2(__hsub2(a1, b1));
                Bh[ib]       = __half_as_ushort(__low2half(d0));
                Bh[ib + 36]  = __half_as_ushort(__high2half(d0));
                Bh[ib + 72]  = __half_as_ushort(__low2half(d1));
                Bh[ib + 108] = __half_as_ushort(__high2half(d1));
            } else {
                Bh[ib] = 0; Bh[ib + 36] = 0; Bh[ib + 72] = 0; Bh[ib + 108] = 0;
            }
        }
        for (int i = t; i < 32 * 288; i += 256) {
            int co = i / 288, kp = i % 288;
            int tap = kp >> 5, cl = kp & 31;
            Ah[co * 296 + kp] =
                __half_as_ushort(__float2half_rn(wD[co * 1152 + (c0 + cl) * 9 + tap]));
        }
        __syncthreads();

#pragma unroll
        for (int tap = 0; tap < 9; tap++) {
            const int dy = tap / 3, dx = tap % 3;
#pragma unroll
            for (int ks = 0; ks < 2; ks++) {
                uint32_t ahf[2][4];
#pragma unroll
                for (int m = 0; m < 2; m++) {
                    uint32_t ao = (uint32_t)((m * 16 + (l & 15)) * 296
                                  + tap * 32 + ks * 16 + (l >> 4) * 8) * 2;
                    ldmx4(ahf[m], ah0 + ao);
                }
                uint32_t bhf[2][2];
#pragma unroll
                for (int j2 = 0; j2 < 2; j2++) {
                    int px = n0 + j2 * 8 + (l >> 2) + dx;
                    int c  = ks * 16 + (l & 3) * 2;
                    int ib = (dy * 130 + px) * 36 + c;
                    bhf[j2][0] = *(const uint32_t*)&Bh[ib];
                    bhf[j2][1] = *(const uint32_t*)&Bh[ib + 8];
                }
#pragma unroll
                for (int m = 0; m < 2; m++)
#pragma unroll
                    for (int j2 = 0; j2 < 2; j2++)
                        mma16816(acc[m][j2], ahf[m], bhf[j2]);
            }
        }
    }

    __half* outp = g_cat + (long)n * (192 * PP) + (long)160 * PP + y * WW;
#pragma unroll
    for (int m = 0; m < 2; m++) {
        int co = m * 16 + (l >> 2);
        float b0 = bD[co], b1 = bD[co + 8];
#pragma unroll
        for (int j2 = 0; j2 < 2; j2++) {
            int px = n0 + j2 * 8 + (l & 3) * 2;
            *(__half2*)(outp + (long)co * PP + px) =
                __floats2half2_rn(acc[m][j2][0] + b0, acc[m][j2][1] + b0);
            *(__half2*)(outp + (long)(co + 8) * PP + px) =
                __floats2half2_rn(acc[m][j2][2] + b1, acc[m][j2][3] + b1);
        }
    }
}

// =====================================================================
// fdir: 3x3 conv 8->32 on sim as HMMA implicit GEMM (1-term)
// =====================================================================
__global__ void __launch_bounds__(256, 2) fdir_mma_kernel(
    const float* __restrict__ wd, const float* __restrict__ bd)
{
    __shared__ ushort Bs[3 * 130 * 8];   // [row][halo px][ch]
    __shared__ ushort Ah[32 * 88];

    const int t = threadIdx.x, l = t & 31, w = t >> 5;
    const int y = blockIdx.x, n = blockIdx.y;
    const int n0 = w * 16;
    const float* simn = g_sim + (long)n * GG * PP;

    for (int i = t; i < 32 * 88; i += 256) {
        int co = i / 88, kp = i % 88;
        ushort h = 0;
        if (kp < 72) {
            int tap = kp >> 3, c = kp & 7;
            h = __half_as_ushort(__float2half_rn(wd[co * 72 + c * 9 + tap]));
        }
        Ah[i] = h;
    }
    if (t < 48) {
        int r = t >> 4, side = (t >> 3) & 1, c = t & 7;
        Bs[(r * 130 + (side ? 129 : 0)) * 8 + c] = 0;
    }
    for (int i = t; i < 1536; i += 256) {
        int r = i >> 9;
        int c = (i >> 6) & 7;
        int q = i & 63;
        int px = q * 2;
        int ys = y + r - 1;
        int ib = (r * 130 + 1 + px) * 8 + c;
        if (ys >= 0 && ys < HH) {
            float2 v = *(const float2*)(simn + (long)c * PP + ys * WW + px);
            Bs[ib]     = __half_as_ushort(__float2half_rn(v.x));
            Bs[ib + 8] = __half_as_ushort(__float2half_rn(v.y));
        } else {
            Bs[ib] = 0; Bs[ib + 8] = 0;
        }
    }
    __syncthreads();

    const uint32_t ah0 = smem_u32(Ah);

    float acc[2][2][4];
#pragma unroll
    for (int m = 0; m < 2; m++)
#pragma unroll
        for (int j = 0; j < 2; j++)
#pragma unroll
            for (int q = 0; q < 4; q++) acc[m][j][q] = 0.f;

    const int cfrag = (l & 3) * 2;
#pragma unroll
    for (int ks = 0; ks < 5; ks++) {
        uint32_t ahf[2][4];
#pragma unroll
        for (int m = 0; m < 2; m++) {
            uint32_t ao = (uint32_t)((m * 16 + (l & 15)) * 88 + ks * 16 + (l >> 4) * 8) * 2;
            ldmx4(ahf[m], ah0 + ao);
        }
        const int tap_a = 2 * ks, tap_b = 2 * ks + 1;
        const int dya = tap_a / 3, dxa = tap_a % 3;
        const int dyb = tap_b / 3, dxb = tap_b % 3;
        uint32_t bhf[2][2];
#pragma unroll
        for (int j2 = 0; j2 < 2; j2++) {
            int pxb = n0 + j2 * 8 + (l >> 2);
            bhf[j2][0] = *(const uint32_t*)&Bs[((dya * 130) + pxb + dxa) * 8 + cfrag];
            bhf[j2][1] = (tap_b < 9)
                ? *(const uint32_t*)&Bs[((dyb * 130) + pxb + dxb) * 8 + cfrag]
                : 0u;
        }
#pragma unroll
        for (int m = 0; m < 2; m++)
#pragma unroll
            for (int j2 = 0; j2 < 2; j2++)
                mma16816(acc[m][j2], ahf[m], bhf[j2]);
    }

    __half* outp = g_cat + (long)n * (192 * PP) + (long)128 * PP + y * WW;
#pragma unroll
    for (int m = 0; m < 2; m++) {
        int co = m * 16 + (l >> 2);
        float b0 = bd[co], b1 = bd[co + 8];
#pragma unroll
        for (int j2 = 0; j2 < 2; j2++) {
            int px = n0 + j2 * 8 + (l & 3) * 2;
            *(__half2*)(outp + (long)co * PP + px) =
                __floats2half2_rn(acc[m][j2][0] + b0, acc[m][j2][1] + b0);
            *(__half2*)(outp + (long)(co + 8) * PP + px) =
                __floats2half2_rn(acc[m][j2][2] + b1, acc[m][j2][3] + b1);
        }
    }
}

// =====================================================================
// off: 1x1 conv 192->32 as HMMA GEMM (1-term, fp16 input from g_cat)
// =====================================================================
#define OFA_H 12800          // [32][200] ushort
#define OFB_H 16384          // [64][128px] ushort
#define OFF_SMEM (OFA_H + OFB_H)   // 29184

__global__ void __launch_bounds__(256, 2) off_mma_kernel(
    const float* __restrict__ wo, const float* __restrict__ bo)
{
    extern __shared__ char smem[];
    ushort* Ah = (ushort*)smem;
    char*   bhs = smem + OFA_H;

    const int t = threadIdx.x, l = t & 31, w = t >> 5;
    const int n = blockIdx.y, p0 = blockIdx.x * 128;
    const __half* xn = g_cat + (long)n * (192 * PP);

    for (int i = t; i < 32 * 192; i += 256) {
        int co = i / 192, k = i % 192;
        Ah[co * 200 + k] = __half_as_ushort(__float2half_rn(wo[co * 192 + k]));
    }

    float acc[2][2][4];
#pragma unroll
    for (int m = 0; m < 2; m++)
#pragma unroll
        for (int j = 0; j < 2; j++)
#pragma unroll
            for (int q = 0; q < 4; q++) acc[m][j][q] = 0.f;

    const uint32_t ah0 = smem_u32(Ah);
    const uint32_t bh0 = smem_u32(bhs);
    const int brow  = l & 15;
    const int bnoff = w * 16 + (l >> 4) * 8;

    for (int kc = 0; kc < 3; kc++) {
        const int k0 = kc * 64;
        __syncthreads();
#pragma unroll
        for (int i = 0; i < 4; i++) {
            int idx = t + i * 256;
            int k = idx >> 4, ch = idx & 15;
            const __half* xp = xn + (long)(k0 + k) * PP + p0 + ch * 8;
            *(uint4*)(bhs + swzB(k * 256 + ch * 16)) = *(const uint4*)xp;
        }
        __syncthreads();

#pragma unroll
        for (int ks = 0; ks < 4; ks++) {
            uint32_t ahf[2][4];
#pragma unroll
            for (int m = 0; m < 2; m++) {
                uint32_t ao = (uint32_t)((m * 16 + (l & 15)) * 200
                              + k0 + ks * 16 + (l >> 4) * 8) * 2;
                ldmx4(ahf[m], ah0 + ao);
            }
            uint32_t Bhf[4];
            ldmx4t(Bhf, bh0 + swzB((uint32_t)((brow + ks * 16) * 256 + bnoff * 2)));
#pragma unroll
            for (int m = 0; m < 2; m++)
#pragma unroll
                for (int j2 = 0; j2 < 2; j2++)
                    mma16816(acc[m][j2], ahf[m], &Bhf[j2 * 2]);
        }
    }

    float* outp = g_off + (long)n * (32 * PP) + p0;
#pragma unroll
    for (int m = 0; m < 2; m++) {
        int co = m * 16 + (l >> 2);
        float b0 = bo[co], b1 = bo[co + 8];
#pragma unroll
        for (int j2 = 0; j2 < 2; j2++) {
            int px = w * 16 + j2 * 8 + (l & 3) * 2;
            outp[(long)co * PP + px]           = acc[m][j2][0] + b0;
            outp[(long)co * PP + px + 1]       = acc[m][j2][1] + b0;
            outp[(long)(co + 8) * PP + px]     = acc[m][j2][2] + b1;
            outp[(long)(co + 8) * PP + px + 1] = acc[m][j2][3] + b1;
        }
    }
}

// ---------------- upsample conv+bn(sp) (fp16), relu, into g_cs[128:] ----------------
__global__ void __launch_bounds__(256) up_relu_kernel()
{
    long gid = (long)blockIdx.x * 256 + threadIdx.x;
    int x = gid & 127;
    int y = (gid >> 7) & 127;
    int c = (int)((gid >> 14) & 127);
    int n = (int)(gid >> 21);
    float ysf = y * (63.f / 127.f);
    int y0 = (int)ysf; float wy = ysf - y0; int y1 = min(y0 + 1, 63);
    float xsf = x * (63.f / 127.f);
    int x0 = (int)xsf; float wx = xsf - x0; int x1 = min(x0 + 1, 63);
    const __half* b = g_tsp + ((long)n * C2 + c) * PS;
    float v = (__half2float(b[y0*WS + x0]) * (1.f - wx) + __half2float(b[y0*WS + x1]) * wx) * (1.f - wy)
            + (__half2float(b[y1*WS + x0]) * (1.f - wx) + __half2float(b[y1*WS + x1]) * wx) * wy;
    g_cs[(long)n * (2*C2*PP) + (long)(C2 + c) * PP + (y * WW + x)] =
        __float2half_rn(fmaxf(v, 0.f));
}

// ---------------- group cosine similarity (fp16 inputs, 2 px/thread) ----------------
__global__ void __launch_bounds__(256) sim_kernel()
{
    long gid = (long)blockIdx.x * 256 + threadIdx.x;  // over NN*GG*PP/2
    int p2 = (int)(gid & (PP/2 - 1));
    int g  = (int)((gid >> 13) & 7);
    int n  = (int)(gid >> 16);
    const __half* a = g_cs + (long)n * (2*C2*PP) + (long)(g * 16) * PP + 2 * p2;
    const __half* b = a + (long)C2 * PP;
    float2 num = {0.f, 0.f}, na = {0.f, 0.f}, nb = {0.f, 0.f};
#pragma unroll
    for (int cc = 0; cc < 16; cc++) {
        float2 af = __half22float2(*(const __half2*)(a + (long)cc * PP));
        float2 bf = __half22float2(*(const __half2*)(b + (long)cc * PP));
        num.x += af.x * bf.x; num.y += af.y * bf.y;
        na.x  += af.x * af.x; na.y  += af.y * af.y;
        nb.x  += bf.x * bf.x; nb.y  += bf.y * bf.y;
    }
    float2 s;
    s.x = num.x / (fmaxf(sqrtf(na.x), 1e-8f) * fmaxf(sqrtf(nb.x), 1e-8f));
    s.y = num.y / (fmaxf(sqrtf(na.y), 1e-8f) * fmaxf(sqrtf(nb.y), 1e-8f));
    *(float2*)(g_sim + gid * 2) = s;
}

// ---------------- final: dual grid_sample + add (sp fused, spill-free 3x3 stencil) ----------------
__device__ __forceinline__ void make_taps(int x, int y, float ox, float oy,
                                          int* tx, int* ty, float* wgt)
{
    float gx = x * (2.f / 127.f) - 1.f + ox * (1.f / 128.f);
    float gy = y * (2.f / 127.f) - 1.f + oy * (1.f / 128.f);
    float px = (gx + 1.f) * 0.5f * 127.f;
    float py = (gy + 1.f) * 0.5f * 127.f;
    float x0f = floorf(px), y0f = floorf(py);
    float wx = px - x0f, wy = py - y0f;
    int x0 = (int)x0f, y0 = (int)y0f, x1 = x0 + 1, y1 = y0 + 1;
    bool vx0 = (x0 >= 0) && (x0 <= 127), vx1 = (x1 >= 0) && (x1 <= 127);
    bool vy0 = (y0 >= 0) && (y0 <= 127), vy1 = (y1 >= 0) && (y1 <= 127);
    int cx0 = min(max(x0, 0), 127), cx1 = min(max(x1, 0), 127);
    int cy0 = min(max(y0, 0), 127), cy1 = min(max(y1, 0), 127);
    tx[0] = cx0; ty[0] = cy0; wgt[0] = (vx0 && vy0) ? (1.f - wx) * (1.f - wy) : 0.f;
    tx[1] = cx1; ty[1] = cy0; wgt[1] = (vx1 && vy0) ? wx * (1.f - wy) : 0.f;
    tx[2] = cx0; ty[2] = cy1; wgt[2] = (vx0 && vy1) ? (1.f - wx) * wy : 0.f;
    tx[3] = cx1; ty[3] = cy1; wgt[3] = (vx1 && vy1) ? wx * wy : 0.f;
}

__global__ void __launch_bounds__(128) sample_kernel(const float* __restrict__ cp,
                                                     const float* __restrict__ sp,
                                                     float* __restrict__ out)
{
    int x  = threadIdx.x;
    int y  = blockIdx.x;
    int ng = blockIdx.y;
    int n  = ng >> 3, gi = ng & 7;
    int p  = (y << 7) | x;
    const float* offn = g_off + (long)n * (32*PP) + p;
    float olx = offn[(long)(2*gi)      * PP];
    float oly = offn[(long)(2*gi + 1)  * PP];
    float ohx = offn[(long)(16 + 2*gi) * PP];
    float ohy = offn[(long)(17 + 2*gi) * PP];

    int lx[4], ly[4], hx[4], hy[4];
    float wl[4], wh[4];
    make_taps(x, y, olx, oly, lx, ly, wl);
    make_taps(x, y, ohx, ohy, hx, hy, wh);

    int il[4];
#pragma unroll
    for (int k = 0; k < 4; k++) il[k] = ly[k] * WW + lx[k];

    // 4 fine sp taps -> 16 coarse taps, all inside one 3x3 coarse window
    // (coarse map slope 63/127 < 1). Accumulate into 9 weights with STATIC
    // destination indices (predicated adds) so everything stays in registers.
    int r0a[4], c0a[4], r1a[4], c1a[4];
    float cwx[4], cwy[4];
    int xmin = 64, ymin = 64;
#pragma unroll
    for (int k = 0; k < 4; k++) {
        float ysf = hy[k] * (63.f / 127.f);
        int y0 = (int)ysf; cwy[k] = ysf - y0;
        r0a[k] = y0; r1a[k] = min(y0 + 1, 63);
        float xsf = hx[k] * (63.f / 127.f);
        int x0 = (int)xsf; cwx[k] = xsf - x0;
        c0a[k] = x0; c1a[k] = min(x0 + 1, 63);
        ymin = min(ymin, y0); xmin = min(xmin, x0);
    }
    float ws00 = 0.f, ws01 = 0.f, ws02 = 0.f;
    float ws10 = 0.f, ws11 = 0.f, ws12 = 0.f;
    float ws20 = 0.f, ws21 = 0.f, ws22 = 0.f;
#pragma unroll
    for (int k = 0; k < 4; k++) {
        float wk = wh[k];
        int r0 = r0a[k] - ymin, c0 = c0a[k] - xmin;   // 0..1
        int r1 = r1a[k] - ymin, c1 = c1a[k] - xmin;   // 0..2
        float wx = cwx[k], wy = cwy[k];
        float w00 = wk * (1.f - wx) * (1.f - wy);
        float w01 = wk * wx * (1.f - wy);
        float w10 = wk * (1.f - wx) * wy;
        float w11 = wk * wx * wy;
        // r0,c0 in {0,1}; r1,c1 in {0,1,2}
        ws00 += ((r0 == 0) & (c0 == 0)) ? w00 : 0.f;
        ws01 += ((r0 == 0) & (c0 == 1)) ? w00 : 0.f;
        ws10 += ((r0 == 1) & (c0 == 0)) ? w00 : 0.f;
        ws11 += ((r0 == 1) & (c0 == 1)) ? w00 : 0.f;

        ws00 += ((r0 == 0) & (c1 == 0)) ? w01 : 0.f;
        ws01 += ((r0 == 0) & (c1 == 1)) ? w01 : 0.f;
        ws02 += ((r0 == 0) & (c1 == 2)) ? w01 : 0.f;
        ws10 += ((r0 == 1) & (c1 == 0)) ? w01 : 0.f;
        ws11 += ((r0 == 1) & (c1 == 1)) ? w01 : 0.f;
        ws12 += ((r0 == 1) & (c1 == 2)) ? w01 : 0.f;

        ws00 += ((r1 == 0) & (c0 == 0)) ? w10 : 0.f;
        ws01 += ((r1 == 0) & (c0 == 1)) ? w10 : 0.f;
        ws10 += ((r1 == 1) & (c0 == 0)) ? w10 : 0.f;
        ws11 += ((r1 == 1) & (c0 == 1)) ? w10 : 0.f;
        ws20 += ((r1 == 2) & (c0 == 0)) ? w10 : 0.f;
        ws21 += ((r1 == 2) & (c0 == 1)) ? w10 : 0.f;

        ws00 += ((r1 == 0) & (c1 == 0)) ? w11 : 0.f;
        ws01 += ((r1 == 0) & (c1 == 1)) ? w11 : 0.f;
        ws02 += ((r1 == 0) & (c1 == 2)) ? w11 : 0.f;
        ws10 += ((r1 == 1) & (c1 == 0)) ? w11 : 0.f;
        ws11 += ((r1 == 1) & (c1 == 1)) ? w11 : 0.f;
        ws12 += ((r1 == 1) & (c1 == 2)) ? w11 : 0.f;
        ws20 += ((r1 == 2) & (c1 == 0)) ? w11 : 0.f;
        ws21 += ((r1 == 2) & (c1 == 1)) ? w11 : 0.f;
        ws22 += ((r1 == 2) & (c1 == 2)) ? w11 : 0.f;
    }
    // static clamped addresses (zero-weight slots may duplicate valid ones)
    const int yr0 = ymin,              yr1 = min(ymin + 1, 63), yr2 = min(ymin + 2, 63);
    const int xc0 = xmin,              xc1 = min(xmin + 1, 63), xc2 = min(xmin + 2, 63);
    const int s00 = yr0 * WS + xc0, s01 = yr0 * WS + xc1, s02 = yr0 * WS + xc2;
    const int s10 = yr1 * WS + xc0, s11 = yr1 * WS + xc1, s12 = yr1 * WS + xc2;
    const int s20 = yr2 * WS + xc0, s21 = yr2 * WS + xc1, s22 = yr2 * WS + xc2;

    long cb_cp = ((long)n * CIN + gi * 32) * PP;
    long cb_sp = ((long)n * CIN + gi * 32) * PS;
    const float* cpp = cp + cb_cp;
    const float* spp = sp + cb_sp;
    float* op = out + cb_cp + p;
#pragma unroll 2
    for (int c = 0; c < 32; c++) {
        const float* a = cpp + (long)c * PP;
        const float* s = spp + (long)c * PS;
        float v = wl[0]*a[il[0]] + wl[1]*a[il[1]] + wl[2]*a[il[2]] + wl[3]*a[il[3]];
        v += ws00 * s[s00] + ws01 * s[s01] + ws02 * s[s02]
           + ws10 * s[s10] + ws11 * s[s11] + ws12 * s[s12]
           + ws20 * s[s20] + ws21 * s[s21] + ws22 * s[s22];
        op[(long)c * PP] = v;
    }
}

// ---------------- persistent host-side stream/event handles ----------------
static cudaStream_t g_s1 = nullptr, g_s2 = nullptr;
static cudaEvent_t  g_e0, g_e1, g_e2, g_e3, g_e4;
static bool g_init_done = false;

// ---------------- launch (fork/join stream overlap, capture-safe) ----------------
extern "C" void kernel_launch(void* const* d_in, const int* in_sizes, int n_in,
                              void* d_out, int out_size)
{
    const float* cp      = (const float*)d_in[0];
    const float* sp      = (const float*)d_in[1];
    const float* w_cp    = (const float*)d_in[2];
    const float* gb_cp   = (const float*)d_in[3];
    const float* b_cp    = (const float*)d_in[4];
    const float* w_sp    = (const float*)d_in[5];
    const float* gb_sp   = (const float*)d_in[6];
    const float* b_sp    = (const float*)d_in[7];
    const float* w_redim = (const float*)d_in[8];
    const float* b_redim = (const float*)d_in[9];
    const float* w_dir   = (const float*)d_in[10];
    const float* b_dir   = (const float*)d_in[11];
    const float* w_dist  = (const float*)d_in[12];
    const float* b_dist  = (const float*)d_in[13];
    const float* w_off   = (const float*)d_in[14];
    const float* b_off   = (const float*)d_in[15];
    float* out = (float*)d_out;

    __half *p_tsp, *p_cs, *p_cat;
    cudaGetSymbolAddress((void**)&p_tsp, g_tsp);
    cudaGetSymbolAddress((void**)&p_cs,  g_cs);
    cudaGetSymbolAddress((void**)&p_cat, g_cat);

    if (!g_init_done) {
        cudaStreamCreateWithFlags(&g_s1, cudaStreamNonBlocking);
        cudaStreamCreateWithFlags(&g_s2, cudaStreamNonBlocking);
        cudaEventCreateWithFlags(&g_e0, cudaEventDisableTiming);
        cudaEventCreateWithFlags(&g_e1, cudaEventDisableTiming);
        cudaEventCreateWithFlags(&g_e2, cudaEventDisableTiming);
        cudaEventCreateWithFlags(&g_e3, cudaEventDisableTiming);
        cudaEventCreateWithFlags(&g_e4, cudaEventDisableTiming);
        cudaFuncSetAttribute(gemm_mma_kernel<float, __half>,
                             cudaFuncAttributeMaxDynamicSharedMemorySize, GEMM_SMEM);
        cudaFuncSetAttribute(gemm_mma_kernel<__half, __half>,
                             cudaFuncAttributeMaxDynamicSharedMemorySize, GEMM_SMEM);
        cudaFuncSetAttribute(fdist_mma_kernel,
                             cudaFuncAttributeMaxDynamicSharedMemorySize, FD_SMEM);
        cudaFuncSetAttribute(off_mma_kernel,
                             cudaFuncAttributeMaxDynamicSharedMemorySize, OFF_SMEM);
        g_init_done = true;
    }
    cudaStream_t s1 = g_s1, s2 = g_s2;

    // ---- phase 1: {sp-gemm -> up_relu} on s1  ||  {cp-gemm} on default ----
    cudaEventRecord(g_e0, 0);
    cudaStreamWaitEvent(s1, g_e0, 0);

    gemm_mma_kernel<float, __half><<<dim3(PS/128, NN), 256, GEMM_SMEM, s1>>>(
        sp, w_sp, gb_sp, b_sp, p_tsp, PS, (long)CIN*PS, (long)C2*PS, 0);
    up_relu_kernel<<<NN*C2*PP/256, 256, 0, s1>>>();

    gemm_mma_kernel<float, __half><<<dim3(PP/128, NN), 256, GEMM_SMEM>>>(
        cp, w_cp, gb_cp, b_cp, p_cs, PP, (long)CIN*PP, (long)2*C2*PP, 1);

    cudaEventRecord(g_e1, s1);
    cudaStreamWaitEvent(0, g_e1, 0);

    // ---- phase 2: {redim} on default || {sim -> fdir} on s1 || {fdist} on s2 ----
    cudaEventRecord(g_e2, 0);
    cudaStreamWaitEvent(s1, g_e2, 0);
    cudaStreamWaitEvent(s2, g_e2, 0);

    gemm_mma_kernel<__half, __half><<<dim3(PP/128, NN), 256, GEMM_SMEM>>>(
        p_cs, w_redim, nullptr, b_redim, p_cat, PP, (long)2*C2*PP, (long)192*PP, 0);

    sim_kernel<<<NN*GG*(PP/2)/256, 256, 0, s1>>>();
    fdir_mma_kernel<<<dim3(HH, NN), 256, 0, s1>>>(w_dir, b_dir);

    fdist_mma_kernel<<<dim3(HH, NN), 256, FD_SMEM, s2>>>(w_dist, b_dist);

    cudaEventRecord(g_e3, s1);
    cudaEventRecord(g_e4, s2);
    cudaStreamWaitEvent(0, g_e3, 0);
    cudaStreamWaitEvent(0, g_e4, 0);

    // ---- phase 3: off -> sample on default ----
    off_mma_kernel<<<dim3(PP/128, NN), 256, OFF_SMEM>>>(w_off, b_off);
    sample_kernel<<<dim3(HH, NN*GG), 128>>>(cp, sp, out);
}

// round 17
// speedup vs baseline: 1.0238x; 1.0118x over previous
#include <cuda_runtime.h>
#include <cuda_fp16.h>
#include <math.h>
#include <stdint.h>

// ---------------- problem constants ----------------
#define NN   8
#define CIN  256
#define C2   128
#define HH   128
#define WW   128
#define GG   8
#define PP   (HH*WW)      // 16384
#define HS   64
#define WS   64
#define PS   (HS*WS)      // 4096

// ---------------- scratch (device globals; no allocation) ----------------
__device__ __half g_tsp [NN*C2*PS];     // conv+bn(sp) at 64x64, fp16
__device__ __half g_cs  [NN*2*C2*PP];   // [cp1 | sp1] 256ch, fp16
__device__ __half g_cat [NN*192*PP];    // [redim(128) | fdir(32) | fdist(32)], fp16
__device__ float  g_sim [NN*GG*PP];
__device__ float  g_off [NN*32*PP];

// =====================================================================
// shared MMA helpers (1-term fp16: weights and inputs rounded once)
// =====================================================================
#define GEMM_SMEM 49152    // A 16KB + B double buffer 2x16KB

__device__ __forceinline__ uint32_t smem_u32(const void* p) {
    uint32_t a;
    asm("{ .reg .u64 t; cvta.to.shared.u64 t, %1; cvt.u32.u64 %0, t; }"
        : "=r"(a) : "l"(p));
    return a;
}
__device__ __forceinline__ uint32_t pack2h(float a, float b) {
    return (uint32_t)__half_as_ushort(__float2half_rn(a))
         | ((uint32_t)__half_as_ushort(__float2half_rn(b)) << 16);
}
__device__ __forceinline__ void cpasync16(uint32_t saddr, const void* g) {
    asm volatile("cp.async.cg.shared.global [%0], [%1], 16;" :: "r"(saddr), "l"(g));
}
__device__ __forceinline__ void ldmx4(uint32_t* r, uint32_t addr) {
    asm volatile("ldmatrix.sync.aligned.m8n8.x4.shared.b16 {%0,%1,%2,%3}, [%4];"
                 : "=r"(r[0]), "=r"(r[1]), "=r"(r[2]), "=r"(r[3]) : "r"(addr));
}
__device__ __forceinline__ void ldmx4t(uint32_t* r, uint32_t addr) {
    asm volatile("ldmatrix.sync.aligned.m8n8.x4.trans.shared.b16 {%0,%1,%2,%3}, [%4];"
                 : "=r"(r[0]), "=r"(r[1]), "=r"(r[2]), "=r"(r[3]) : "r"(addr));
}
__device__ __forceinline__ void mma16816(float* c, const uint32_t* a, const uint32_t* b) {
    asm volatile("mma.sync.aligned.m16n8k16.row.col.f32.f16.f16.f32 "
                 "{%0,%1,%2,%3}, {%4,%5,%6,%7}, {%8,%9}, {%0,%1,%2,%3};"
                 : "+f"(c[0]), "+f"(c[1]), "+f"(c[2]), "+f"(c[3])
                 : "r"(a[0]), "r"(a[1]), "r"(a[2]), "r"(a[3]), "r"(b[0]), "r"(b[1]));
}
__device__ __forceinline__ uint32_t swzA(uint32_t bo) { return bo ^ (((bo >> 7) & 7) << 4); }
__device__ __forceinline__ uint32_t swzB(uint32_t bo) { return bo ^ (((bo >> 8) & 7) << 4); }

// =====================================================================
// 128-out 1x1 conv GEMM (1-term fp16), templated input/output dtype.
// fp16-input path: B staged via cp.async with double buffering.
// =====================================================================
template<typename TIN, typename TOUT>
__global__ void __launch_bounds__(256, 2) gemm_mma_kernel(
    const TIN* __restrict__ X, const float* __restrict__ Wm,
    const float* __restrict__ gscale, const float* __restrict__ bias,
    TOUT* __restrict__ Y, int Pn, long xns, long yns, int relu)
{
    extern __shared__ char smem[];
    char* ahs  = smem;               // [128co][64k] fp16  16KB
    char* bhs0 = smem + 16384;       // B buffer 0         16KB
    char* bhs1 = smem + 32768;       // B buffer 1         16KB

    const int t  = threadIdx.x;
    const int l  = t & 31, w = t >> 5;
    const int wm = w & 1, wn = w >> 1;
    const int n  = blockIdx.y, p0 = blockIdx.x * 128;
    const TIN* Xn = X + (long)n * xns;
    TOUT*      Yn = Y + (long)n * yns;

    const uint32_t ah0 = smem_u32(ahs);

    float acc[4][4][4];
#pragma unroll
    for (int i = 0; i < 4; i++)
#pragma unroll
        for (int j = 0; j < 4; j++)
#pragma unroll
            for (int q = 0; q < 4; q++) acc[i][j][q] = 0.f;

    const int arow  = wm * 64 + (l & 15);
    const int akoff = (l >> 4) * 8;
    const int brow  = (l & 15);
    const int bnoff = wn * 32 + (l >> 4) * 8;

    // prologue: prefetch B chunk 0 (fp16 path)
    if constexpr (sizeof(TIN) == 2) {
        const uint32_t b0a = smem_u32(bhs0);
#pragma unroll
        for (int i = 0; i < 4; i++) {
            int idx = t + i * 256;
            int k = idx >> 4, ch = idx & 15;
            const __half* xp = (const __half*)Xn + (long)k * Pn + p0 + ch * 8;
            cpasync16(b0a + swzB(k * 256 + ch * 16), xp);
        }
        asm volatile("cp.async.commit_group;" ::: "memory");
    }

#pragma unroll
    for (int c = 0; c < 4; c++) {
        const int k0 = c * 64;
        __syncthreads();
        // ---- stage A (weights, fp16) ----
#pragma unroll
        for (int i = 0; i < 4; i++) {
            int idx = t + i * 256;
            int row = idx >> 3, ch = idx & 7;
            const float* wp = Wm + (long)row * 256 + k0 + ch * 8;
            float4 v0 = *(const float4*)wp;
            float4 v1 = *(const float4*)(wp + 4);
            uint4 h4;
            h4.x = pack2h(v0.x, v0.y);
            h4.y = pack2h(v0.z, v0.w);
            h4.z = pack2h(v1.x, v1.y);
            h4.w = pack2h(v1.z, v1.w);
            *(uint4*)(ahs + swzA(row * 128 + ch * 16)) = h4;
        }
        // ---- stage B ----
        if constexpr (sizeof(TIN) == 2) {
            if (c < 3) {
                char* bn = ((c + 1) & 1) ? bhs1 : bhs0;
                const uint32_t bna = smem_u32(bn);
#pragma unroll
                for (int i = 0; i < 4; i++) {
                    int idx = t + i * 256;
                    int k = idx >> 4, ch = idx & 15;
                    const __half* xp = (const __half*)Xn + (long)(k0 + 64 + k) * Pn + p0 + ch * 8;
                    cpasync16(bna + swzB(k * 256 + ch * 16), xp);
                }
                asm volatile("cp.async.commit_group;" ::: "memory");
                asm volatile("cp.async.wait_group 1;" ::: "memory");
            } else {
                asm volatile("cp.async.wait_group 0;" ::: "memory");
            }
        } else {
#pragma unroll
            for (int i = 0; i < 4; i++) {
                int idx = t + i * 256;
                int k = idx >> 4, ch = idx & 15;
                const float* xp = (const float*)Xn + (long)(k0 + k) * Pn + p0 + ch * 8;
                float4 v0 = *(const float4*)xp;
                float4 v1 = *(const float4*)(xp + 4);
                uint4 h4;
                h4.x = pack2h(v0.x, v0.y);
                h4.y = pack2h(v0.z, v0.w);
                h4.z = pack2h(v1.x, v1.y);
                h4.w = pack2h(v1.z, v1.w);
                *(uint4*)(bhs0 + swzB(k * 256 + ch * 16)) = h4;
            }
        }
        __syncthreads();

        const uint32_t bh0 = (sizeof(TIN) == 2)
            ? smem_u32((c & 1) ? bhs1 : bhs0)
            : smem_u32(bhs0);

#pragma unroll
        for (int ks = 0; ks < 4; ks++) {
            uint32_t a[4][4];
            uint32_t B[2][4];
#pragma unroll
            for (int i = 0; i < 4; i++) {
                uint32_t bo = (uint32_t)((arow + i * 16) * 128 + (akoff + ks * 16) * 2);
                ldmx4(a[i], ah0 + swzA(bo));
            }
#pragma unroll
            for (int j2 = 0; j2 < 2; j2++) {
                uint32_t bo = (uint32_t)((brow + ks * 16) * 256 + (bnoff + j2 * 16) * 2);
                ldmx4t(B[j2], bh0 + swzB(bo));
            }
#pragma unroll
            for (int i = 0; i < 4; i++)
#pragma unroll
                for (int j = 0; j < 4; j++)
                    mma16816(acc[i][j], a[i], &B[j >> 1][(j & 1) * 2]);
        }
    }

    const float bnfac = rsqrtf(1.f + 1e-5f);
    const int gid = l >> 2, tig = l & 3;
#pragma unroll
    for (int i = 0; i < 4; i++) {
        int co0 = wm * 64 + i * 16 + gid;
        int co1 = co0 + 8;
        float s0 = gscale ? gscale[co0] * bnfac : 1.f;
        float s1 = gscale ? gscale[co1] * bnfac : 1.f;
        float b0 = bias[co0], b1 = bias[co1];
#pragma unroll
        for (int j = 0; j < 4; j++) {
            int col = p0 + wn * 32 + j * 8 + 2 * tig;
            float2 r0, r1;
            r0.x = acc[i][j][0] * s0 + b0;
            r0.y = acc[i][j][1] * s0 + b0;
            r1.x = acc[i][j][2] * s1 + b1;
            r1.y = acc[i][j][3] * s1 + b1;
            if (relu) {
                r0.x = fmaxf(r0.x, 0.f); r0.y = fmaxf(r0.y, 0.f);
                r1.x = fmaxf(r1.x, 0.f); r1.y = fmaxf(r1.y, 0.f);
            }
            if constexpr (sizeof(TOUT) == 4) {
                *(float2*)((float*)Yn + (long)co0 * Pn + col) = r0;
                *(float2*)((float*)Yn + (long)co1 * Pn + col) = r1;
            } else {
                *(__half2*)((__half*)Yn + (long)co0 * Pn + col) = __floats2half2_rn(r0.x, r0.y);
                *(__half2*)((__half*)Yn + (long)co1 * Pn + col) = __floats2half2_rn(r1.x, r1.y);
            }
        }
    }
}

// =====================================================================
// fdist: 3x3 conv 128->32 on |cp1-sp1| (fp16) as HMMA implicit GEMM (1-term)
// =====================================================================
#define FDB_H   28160      // [3][130][36] ushort
#define FDA_H   18944      // [32][296] ushort
#define FD_SMEM (FDB_H + FDA_H)   // 47104

__global__ void __launch_bounds__(256, 2) fdist_mma_kernel(
    const float* __restrict__ wD, const float* __restrict__ bD)
{
    extern __shared__ char smem[];
    ushort* Bh = (ushort*)smem;
    ushort* Ah = (ushort*)(smem + FDB_H);

    const int t = threadIdx.x, l = t & 31, w = t >> 5;
    const int y = blockIdx.x, n = blockIdx.y;
    const int n0 = w * 16;
    const __half* csn = g_cs + (long)n * (2*C2*PP);

    float acc[2][2][4];
#pragma unroll
    for (int m = 0; m < 2; m++)
#pragma unroll
        for (int j = 0; j < 2; j++)
#pragma unroll
            for (int q = 0; q < 4; q++) acc[m][j][q] = 0.f;

    const uint32_t ah0 = smem_u32(Ah);

    for (int c0 = 0; c0 < C2; c0 += 32) {
        __syncthreads();
        if (t < 96) {
            int r = t >> 5, c = t & 31;
            Bh[(r * 130 + 0)   * 36 + c] = 0;
            Bh[(r * 130 + 129) * 36 + c] = 0;
        }
        for (int i = t; i < 3072; i += 256) {
            int r = i >> 10;
            int c = (i >> 5) & 31;
            int q = i & 31;
            int ys = y + r - 1;
            int px = q * 4;
            int ib = (r * 130 + 1 + px) * 36 + c;
            if (ys >= 0 && ys < HH) {
                long off = (long)(c0 + c) * PP + ys * WW + px;
                __half2 a0 = *(const __half2*)(csn + off);
                __half2 a1 = *(const __half2*)(csn + off + 2);
                __half2 b0 = *(const __half2*)(csn + off + (long)C2 * PP);
                __half2 b1 = *(const __half2*)(csn + off + (long)C2 * PP + 2);
                __half2 d0 = __habs2(__hsub2(a0, b0));
                __half2 d1 = __habs2(__hsub2(a1, b1));
                Bh[ib]       = __half_as_ushort(__low2half(d0));
                Bh[ib + 36]  = __half_as_ushort(__high2half(d0));
                Bh[ib + 72]  = __half_as_ushort(__low2half(d1));
                Bh[ib + 108] = __half_as_ushort(__high2half(d1));
            } else {
                Bh[ib] = 0; Bh[ib + 36] = 0; Bh[ib + 72] = 0; Bh[ib + 108] = 0;
            }
        }
        for (int i = t; i < 32 * 288; i += 256) {
            int co = i / 288, kp = i % 288;
            int tap = kp >> 5, cl = kp & 31;
            Ah[co * 296 + kp] =
                __half_as_ushort(__float2half_rn(wD[co * 1152 + (c0 + cl) * 9 + tap]));
        }
        __syncthreads();

#pragma unroll
        for (int tap = 0; tap < 9; tap++) {
            const int dy = tap / 3, dx = tap % 3;
#pragma unroll
            for (int ks = 0; ks < 2; ks++) {
                uint32_t ahf[2][4];
#pragma unroll
                for (int m = 0; m < 2; m++) {
                    uint32_t ao = (uint32_t)((m * 16 + (l & 15)) * 296
                                  + tap * 32 + ks * 16 + (l >> 4) * 8) * 2;
                    ldmx4(ahf[m], ah0 + ao);
                }
                uint32_t bhf[2][2];
#pragma unroll
                for (int j2 = 0; j2 < 2; j2++) {
                    int px = n0 + j2 * 8 + (l >> 2) + dx;
                    int c  = ks * 16 + (l & 3) * 2;
                    int ib = (dy * 130 + px) * 36 + c;
                    bhf[j2][0] = *(const uint32_t*)&Bh[ib];
                    bhf[j2][1] = *(const uint32_t*)&Bh[ib + 8];
                }
#pragma unroll
                for (int m = 0; m < 2; m++)
#pragma unroll
                    for (int j2 = 0; j2 < 2; j2++)
                        mma16816(acc[m][j2], ahf[m], bhf[j2]);
            }
        }
    }

    __half* outp = g_cat + (long)n * (192 * PP) + (long)160 * PP + y * WW;
#pragma unroll
    for (int m = 0; m < 2; m++) {
        int co = m * 16 + (l >> 2);
        float b0 = bD[co], b1 = bD[co + 8];
#pragma unroll
        for (int j2 = 0; j2 < 2; j2++) {
            int px = n0 + j2 * 8 + (l & 3) * 2;
            *(__half2*)(outp + (long)co * PP + px) =
                __floats2half2_rn(acc[m][j2][0] + b0, acc[m][j2][1] + b0);
            *(__half2*)(outp + (long)(co + 8) * PP + px) =
                __floats2half2_rn(acc[m][j2][2] + b1, acc[m][j2][3] + b1);
        }
    }
}

// =====================================================================
// fdir: 3x3 conv 8->32 on sim as HMMA implicit GEMM (1-term)
// =====================================================================
__global__ void __launch_bounds__(256, 2) fdir_mma_kernel(
    const float* __restrict__ wd, const float* __restrict__ bd)
{
    __shared__ ushort Bs[3 * 130 * 8];   // [row][halo px][ch]
    __shared__ ushort Ah[32 * 88];

    const int t = threadIdx.x, l = t & 31, w = t >> 5;
    const int y = blockIdx.x, n = blockIdx.y;
    const int n0 = w * 16;
    const float* simn = g_sim + (long)n * GG * PP;

    for (int i = t; i < 32 * 88; i += 256) {
        int co = i / 88, kp = i % 88;
        ushort h = 0;
        if (kp < 72) {
            int tap = kp >> 3, c = kp & 7;
            h = __half_as_ushort(__float2half_rn(wd[co * 72 + c * 9 + tap]));
        }
        Ah[i] = h;
    }
    if (t < 48) {
        int r = t >> 4, side = (t >> 3) & 1, c = t & 7;
        Bs[(r * 130 + (side ? 129 : 0)) * 8 + c] = 0;
    }
    for (int i = t; i < 1536; i += 256) {
        int r = i >> 9;
        int c = (i >> 6) & 7;
        int q = i & 63;
        int px = q * 2;
        int ys = y + r - 1;
        int ib = (r * 130 + 1 + px) * 8 + c;
        if (ys >= 0 && ys < HH) {
            float2 v = *(const float2*)(simn + (long)c * PP + ys * WW + px);
            Bs[ib]     = __half_as_ushort(__float2half_rn(v.x));
            Bs[ib + 8] = __half_as_ushort(__float2half_rn(v.y));
        } else {
            Bs[ib] = 0; Bs[ib + 8] = 0;
        }
    }
    __syncthreads();

    const uint32_t ah0 = smem_u32(Ah);

    float acc[2][2][4];
#pragma unroll
    for (int m = 0; m < 2; m++)
#pragma unroll
        for (int j = 0; j < 2; j++)
#pragma unroll
            for (int q = 0; q < 4; q++) acc[m][j][q] = 0.f;

    const int cfrag = (l & 3) * 2;
#pragma unroll
    for (int ks = 0; ks < 5; ks++) {
        uint32_t ahf[2][4];
#pragma unroll
        for (int m = 0; m < 2; m++) {
            uint32_t ao = (uint32_t)((m * 16 + (l & 15)) * 88 + ks * 16 + (l >> 4) * 8) * 2;
            ldmx4(ahf[m], ah0 + ao);
        }
        const int tap_a = 2 * ks, tap_b = 2 * ks + 1;
        const int dya = tap_a / 3, dxa = tap_a % 3;
        const int dyb = tap_b / 3, dxb = tap_b % 3;
        uint32_t bhf[2][2];
#pragma unroll
        for (int j2 = 0; j2 < 2; j2++) {
            int pxb = n0 + j2 * 8 + (l >> 2);
            bhf[j2][0] = *(const uint32_t*)&Bs[((dya * 130) + pxb + dxa) * 8 + cfrag];
            bhf[j2][1] = (tap_b < 9)
                ? *(const uint32_t*)&Bs[((dyb * 130) + pxb + dxb) * 8 + cfrag]
                : 0u;
        }
#pragma unroll
        for (int m = 0; m < 2; m++)
#pragma unroll
            for (int j2 = 0; j2 < 2; j2++)
                mma16816(acc[m][j2], ahf[m], bhf[j2]);
    }

    __half* outp = g_cat + (long)n * (192 * PP) + (long)128 * PP + y * WW;
#pragma unroll
    for (int m = 0; m < 2; m++) {
        int co = m * 16 + (l >> 2);
        float b0 = bd[co], b1 = bd[co + 8];
#pragma unroll
        for (int j2 = 0; j2 < 2; j2++) {
            int px = n0 + j2 * 8 + (l & 3) * 2;
            *(__half2*)(outp + (long)co * PP + px) =
                __floats2half2_rn(acc[m][j2][0] + b0, acc[m][j2][1] + b0);
            *(__half2*)(outp + (long)(co + 8) * PP + px) =
                __floats2half2_rn(acc[m][j2][2] + b1, acc[m][j2][3] + b1);
        }
    }
}

// =====================================================================
// off: 1x1 conv 192->32 as HMMA GEMM (1-term, fp16 input from g_cat)
// =====================================================================
#define OFA_H 12800          // [32][200] ushort
#define OFB_H 16384          // [64][128px] ushort
#define OFF_SMEM (OFA_H + OFB_H)   // 29184

__global__ void __launch_bounds__(256, 2) off_mma_kernel(
    const float* __restrict__ wo, const float* __restrict__ bo)
{
    extern __shared__ char smem[];
    ushort* Ah = (ushort*)smem;
    char*   bhs = smem + OFA_H;

    const int t = threadIdx.x, l = t & 31, w = t >> 5;
    const int n = blockIdx.y, p0 = blockIdx.x * 128;
    const __half* xn = g_cat + (long)n * (192 * PP);

    for (int i = t; i < 32 * 192; i += 256) {
        int co = i / 192, k = i % 192;
        Ah[co * 200 + k] = __half_as_ushort(__float2half_rn(wo[co * 192 + k]));
    }

    float acc[2][2][4];
#pragma unroll
    for (int m = 0; m < 2; m++)
#pragma unroll
        for (int j = 0; j < 2; j++)
#pragma unroll
            for (int q = 0; q < 4; q++) acc[m][j][q] = 0.f;

    const uint32_t ah0 = smem_u32(Ah);
    const uint32_t bh0 = smem_u32(bhs);
    const int brow  = l & 15;
    const int bnoff = w * 16 + (l >> 4) * 8;

    for (int kc = 0; kc < 3; kc++) {
        const int k0 = kc * 64;
        __syncthreads();
#pragma unroll
        for (int i = 0; i < 4; i++) {
            int idx = t + i * 256;
            int k = idx >> 4, ch = idx & 15;
            const __half* xp = xn + (long)(k0 + k) * PP + p0 + ch * 8;
            *(uint4*)(bhs + swzB(k * 256 + ch * 16)) = *(const uint4*)xp;
        }
        __syncthreads();

#pragma unroll
        for (int ks = 0; ks < 4; ks++) {
            uint32_t ahf[2][4];
#pragma unroll
            for (int m = 0; m < 2; m++) {
                uint32_t ao = (uint32_t)((m * 16 + (l & 15)) * 200
                              + k0 + ks * 16 + (l >> 4) * 8) * 2;
                ldmx4(ahf[m], ah0 + ao);
            }
            uint32_t Bhf[4];
            ldmx4t(Bhf, bh0 + swzB((uint32_t)((brow + ks * 16) * 256 + bnoff * 2)));
#pragma unroll
            for (int m = 0; m < 2; m++)
#pragma unroll
                for (int j2 = 0; j2 < 2; j2++)
                    mma16816(acc[m][j2], ahf[m], &Bhf[j2 * 2]);
        }
    }

    float* outp = g_off + (long)n * (32 * PP) + p0;
#pragma unroll
    for (int m = 0; m < 2; m++) {
        int co = m * 16 + (l >> 2);
        float b0 = bo[co], b1 = bo[co + 8];
#pragma unroll
        for (int j2 = 0; j2 < 2; j2++) {
            int px = w * 16 + j2 * 8 + (l & 3) * 2;
            outp[(long)co * PP + px]           = acc[m][j2][0] + b0;
            outp[(long)co * PP + px + 1]       = acc[m][j2][1] + b0;
            outp[(long)(co + 8) * PP + px]     = acc[m][j2][2] + b1;
            outp[(long)(co + 8) * PP + px + 1] = acc[m][j2][3] + b1;
        }
    }
}

// ---------------- upsample conv+bn(sp) (fp16), relu, into g_cs[128:] ----------------
__global__ void __launch_bounds__(256) up_relu_kernel()
{
    long gid = (long)blockIdx.x * 256 + threadIdx.x;
    int x = gid & 127;
    int y = (gid >> 7) & 127;
    int c = (int)((gid >> 14) & 127);
    int n = (int)(gid >> 21);
    float ysf = y * (63.f / 127.f);
    int y0 = (int)ysf; float wy = ysf - y0; int y1 = min(y0 + 1, 63);
    float xsf = x * (63.f / 127.f);
    int x0 = (int)xsf; float wx = xsf - x0; int x1 = min(x0 + 1, 63);
    const __half* b = g_tsp + ((long)n * C2 + c) * PS;
    float v = (__half2float(b[y0*WS + x0]) * (1.f - wx) + __half2float(b[y0*WS + x1]) * wx) * (1.f - wy)
            + (__half2float(b[y1*WS + x0]) * (1.f - wx) + __half2float(b[y1*WS + x1]) * wx) * wy;
    g_cs[(long)n * (2*C2*PP) + (long)(C2 + c) * PP + (y * WW + x)] =
        __float2half_rn(fmaxf(v, 0.f));
}

// ---------------- group cosine similarity (fp16 inputs, 2 px/thread) ----------------
__global__ void __launch_bounds__(256) sim_kernel()
{
    long gid = (long)blockIdx.x * 256 + threadIdx.x;  // over NN*GG*PP/2
    int p2 = (int)(gid & (PP/2 - 1));
    int g  = (int)((gid >> 13) & 7);
    int n  = (int)(gid >> 16);
    const __half* a = g_cs + (long)n * (2*C2*PP) + (long)(g * 16) * PP + 2 * p2;
    const __half* b = a + (long)C2 * PP;
    float2 num = {0.f, 0.f}, na = {0.f, 0.f}, nb = {0.f, 0.f};
#pragma unroll
    for (int cc = 0; cc < 16; cc++) {
        float2 af = __half22float2(*(const __half2*)(a + (long)cc * PP));
        float2 bf = __half22float2(*(const __half2*)(b + (long)cc * PP));
        num.x += af.x * bf.x; num.y += af.y * bf.y;
        na.x  += af.x * af.x; na.y  += af.y * af.y;
        nb.x  += bf.x * bf.x; nb.y  += bf.y * bf.y;
    }
    float2 s;
    s.x = num.x / (fmaxf(sqrtf(na.x), 1e-8f) * fmaxf(sqrtf(nb.x), 1e-8f));
    s.y = num.y / (fmaxf(sqrtf(na.y), 1e-8f) * fmaxf(sqrtf(nb.y), 1e-8f));
    *(float2*)(g_sim + gid * 2) = s;
}

// ---------------- final: dual grid_sample + add (sp upsample fused, R11 form) ----------------
__device__ __forceinline__ void make_taps(int x, int y, float ox, float oy,
                                          int* tx, int* ty, float* wgt)
{
    float gx = x * (2.f / 127.f) - 1.f + ox * (1.f / 128.f);
    float gy = y * (2.f / 127.f) - 1.f + oy * (1.f / 128.f);
    float px = (gx + 1.f) * 0.5f * 127.f;
    float py = (gy + 1.f) * 0.5f * 127.f;
    float x0f = floorf(px), y0f = floorf(py);
    float wx = px - x0f, wy = py - y0f;
    int x0 = (int)x0f, y0 = (int)y0f, x1 = x0 + 1, y1 = y0 + 1;
    bool vx0 = (x0 >= 0) && (x0 <= 127), vx1 = (x1 >= 0) && (x1 <= 127);
    bool vy0 = (y0 >= 0) && (y0 <= 127), vy1 = (y1 >= 0) && (y1 <= 127);
    int cx0 = min(max(x0, 0), 127), cx1 = min(max(x1, 0), 127);
    int cy0 = min(max(y0, 0), 127), cy1 = min(max(y1, 0), 127);
    tx[0] = cx0; ty[0] = cy0; wgt[0] = (vx0 && vy0) ? (1.f - wx) * (1.f - wy) : 0.f;
    tx[1] = cx1; ty[1] = cy0; wgt[1] = (vx1 && vy0) ? wx * (1.f - wy) : 0.f;
    tx[2] = cx0; ty[2] = cy1; wgt[2] = (vx0 && vy1) ? (1.f - wx) * wy : 0.f;
    tx[3] = cx1; ty[3] = cy1; wgt[3] = (vx1 && vy1) ? wx * wy : 0.f;
}

__global__ void __launch_bounds__(128) sample_kernel(const float* __restrict__ cp,
                                                     const float* __restrict__ sp,
                                                     float* __restrict__ out)
{
    int x  = threadIdx.x;
    int y  = blockIdx.x;
    int ng = blockIdx.y;
    int n  = ng >> 3, gi = ng & 7;
    int p  = (y << 7) | x;
    const float* offn = g_off + (long)n * (32*PP) + p;
    float olx = offn[(long)(2*gi)      * PP];
    float oly = offn[(long)(2*gi + 1)  * PP];
    float ohx = offn[(long)(16 + 2*gi) * PP];
    float ohy = offn[(long)(17 + 2*gi) * PP];

    int lx[4], ly[4], hx[4], hy[4];
    float wl[4], wh[4];
    make_taps(x, y, olx, oly, lx, ly, wl);
    make_taps(x, y, ohx, ohy, hx, hy, wh);

    int il[4];
#pragma unroll
    for (int k = 0; k < 4; k++) il[k] = ly[k] * WW + lx[k];

    int ci[16];
    float cw[16];
#pragma unroll
    for (int k = 0; k < 4; k++) {
        float ysf = hy[k] * (63.f / 127.f);
        int y0 = (int)ysf; float wy = ysf - y0; int y1 = min(y0 + 1, 63);
        float xsf = hx[k] * (63.f / 127.f);
        int x0 = (int)xsf; float wx = xsf - x0; int x1 = min(x0 + 1, 63);
        float wk = wh[k];
        ci[k*4+0] = y0 * WS + x0; cw[k*4+0] = wk * (1.f - wx) * (1.f - wy);
        ci[k*4+1] = y0 * WS + x1; cw[k*4+1] = wk * wx * (1.f - wy);
        ci[k*4+2] = y1 * WS + x0; cw[k*4+2] = wk * (1.f - wx) * wy;
        ci[k*4+3] = y1 * WS + x1; cw[k*4+3] = wk * wx * wy;
    }

    long cb_cp = ((long)n * CIN + gi * 32) * PP;
    long cb_sp = ((long)n * CIN + gi * 32) * PS;
    const float* cpp = cp + cb_cp;
    const float* spp = sp + cb_sp;
    float* op = out + cb_cp + p;
#pragma unroll 2
    for (int c = 0; c < 32; c++) {
        const float* a = cpp + (long)c * PP;
        const float* s = spp + (long)c * PS;
        float v = wl[0]*a[il[0]] + wl[1]*a[il[1]] + wl[2]*a[il[2]] + wl[3]*a[il[3]];
#pragma unroll
        for (int k = 0; k < 16; k++) v += cw[k] * s[ci[k]];
        op[(long)c * PP] = v;
    }
}

// ---------------- persistent host-side stream/event handles ----------------
static cudaStream_t g_s1 = nullptr, g_s2 = nullptr;
static cudaEvent_t  g_e0, g_e1, g_e2, g_e3, g_e4;
static bool g_init_done = false;

// ---------------- launch (fork/join stream overlap, capture-safe) ----------------
extern "C" void kernel_launch(void* const* d_in, const int* in_sizes, int n_in,
                              void* d_out, int out_size)
{
    const float* cp      = (const float*)d_in[0];
    const float* sp      = (const float*)d_in[1];
    const float* w_cp    = (const float*)d_in[2];
    const float* gb_cp   = (const float*)d_in[3];
    const float* b_cp    = (const float*)d_in[4];
    const float* w_sp    = (const float*)d_in[5];
    const float* gb_sp   = (const float*)d_in[6];
    const float* b_sp    = (const float*)d_in[7];
    const float* w_redim = (const float*)d_in[8];
    const float* b_redim = (const float*)d_in[9];
    const float* w_dir   = (const float*)d_in[10];
    const float* b_dir   = (const float*)d_in[11];
    const float* w_dist  = (const float*)d_in[12];
    const float* b_dist  = (const float*)d_in[13];
    const float* w_off   = (const float*)d_in[14];
    const float* b_off   = (const float*)d_in[15];
    float* out = (float*)d_out;

    __half *p_tsp, *p_cs, *p_cat;
    cudaGetSymbolAddress((void**)&p_tsp, g_tsp);
    cudaGetSymbolAddress((void**)&p_cs,  g_cs);
    cudaGetSymbolAddress((void**)&p_cat, g_cat);

    if (!g_init_done) {
        cudaStreamCreateWithFlags(&g_s1, cudaStreamNonBlocking);
        cudaStreamCreateWithFlags(&g_s2, cudaStreamNonBlocking);
        cudaEventCreateWithFlags(&g_e0, cudaEventDisableTiming);
        cudaEventCreateWithFlags(&g_e1, cudaEventDisableTiming);
        cudaEventCreateWithFlags(&g_e2, cudaEventDisableTiming);
        cudaEventCreateWithFlags(&g_e3, cudaEventDisableTiming);
        cudaEventCreateWithFlags(&g_e4, cudaEventDisableTiming);
        cudaFuncSetAttribute(gemm_mma_kernel<float, __half>,
                             cudaFuncAttributeMaxDynamicSharedMemorySize, GEMM_SMEM);
        cudaFuncSetAttribute(gemm_mma_kernel<__half, __half>,
                             cudaFuncAttributeMaxDynamicSharedMemorySize, GEMM_SMEM);
        cudaFuncSetAttribute(fdist_mma_kernel,
                             cudaFuncAttributeMaxDynamicSharedMemorySize, FD_SMEM);
        cudaFuncSetAttribute(off_mma_kernel,
                             cudaFuncAttributeMaxDynamicSharedMemorySize, OFF_SMEM);
        g_init_done = true;
    }
    cudaStream_t s1 = g_s1, s2 = g_s2;

    // ---- phase 1: {sp-gemm -> up_relu} on s1  ||  {cp-gemm} on default ----
    cudaEventRecord(g_e0, 0);
    cudaStreamWaitEvent(s1, g_e0, 0);

    gemm_mma_kernel<float, __half><<<dim3(PS/128, NN), 256, GEMM_SMEM, s1>>>(
        sp, w_sp, gb_sp, b_sp, p_tsp, PS, (long)CIN*PS, (long)C2*PS, 0);
    up_relu_kernel<<<NN*C2*PP/256, 256, 0, s1>>>();

    gemm_mma_kernel<float, __half><<<dim3(PP/128, NN), 256, GEMM_SMEM>>>(
        cp, w_cp, gb_cp, b_cp, p_cs, PP, (long)CIN*PP, (long)2*C2*PP, 1);

    cudaEventRecord(g_e1, s1);
    cudaStreamWaitEvent(0, g_e1, 0);

    // ---- phase 2: {redim} on default || {sim -> fdir} on s1 || {fdist} on s2 ----
    cudaEventRecord(g_e2, 0);
    cudaStreamWaitEvent(s1, g_e2, 0);
    cudaStreamWaitEvent(s2, g_e2, 0);

    gemm_mma_kernel<__half, __half><<<dim3(PP/128, NN), 256, GEMM_SMEM>>>(
        p_cs, w_redim, nullptr, b_redim, p_cat, PP, (long)2*C2*PP, (long)192*PP, 0);

    sim_kernel<<<NN*GG*(PP/2)/256, 256, 0, s1>>>();
    fdir_mma_kernel<<<dim3(HH, NN), 256, 0, s1>>>(w_dir, b_dir);

    fdist_mma_kernel<<<dim3(HH, NN), 256, FD_SMEM, s2>>>(w_dist, b_dist);

    cudaEventRecord(g_e3, s1);
    cudaEventRecord(g_e4, s2);
    cudaStreamWaitEvent(0, g_e3, 0);
    cudaStreamWaitEvent(0, g_e4, 0);

    // ---- phase 3: off -> sample on default ----
    off_mma_kernel<<<dim3(PP/128, NN), 256, OFF_SMEM>>>(w_off, b_off);
    sample_kernel<<<dim3(HH, NN*GG), 128>>>(cp, sp, out);
}